// round 12
// baseline (speedup 1.0000x reference)
#include <cuda_runtime.h>
#include <mma.h>
#include <cstdint>
#include <cstddef>

using namespace nvcuda;

#define BATCH 8192
#define FDIM  1024
#define HDIM  256
#define NTASK 8

// ---------------- scratch (static device globals; no allocation) ----------------
__device__ float g_fhi[BATCH * FDIM], g_flo[BATCH * FDIM];   // features tf32 split; reused for final-x split
__device__ float g_W1hi[HDIM * FDIM], g_W1lo[HDIM * FDIM];
__device__ float g_Thi[NTASK * FDIM * FDIM];                 // task mats transposed to [N,K], tf32
__device__ float g_Phi[FDIM * FDIM], g_Plo[FDIM * FDIM];     // projW split ([N,K] layout already)
__device__ float g_xa[BATCH * FDIM];                         // chain x, updated IN PLACE
__device__ float g_xar[BATCH * FDIM], g_xbr[BATCH * FDIM];   // tf32-rounded x ping-pong (A operand)
__device__ float g_hpart[2 * BATCH * HDIM];                  // h split-K partials
__device__ float    g_h[BATCH * HDIM];
__device__ float    g_G[HDIM * HDIM];
__device__ float    g_coeffs[BATCH * NTASK];
__device__ float    g_unc2[BATCH * NTASK];
__device__ unsigned g_max2bits;
__device__ float    g_gated[BATCH * NTASK];
__device__ int      g_cnt[NTASK];
__device__ int      g_idx[NTASK * BATCH];
__device__ unsigned g_notident;

// ---------------- cp.async helpers ----------------
__device__ __forceinline__ void cp16(float* s, const float* g) {
    unsigned sa = (unsigned)__cvta_generic_to_shared(s);
    asm volatile("cp.async.cg.shared.global [%0], [%1], 16;" :: "r"(sa), "l"(g));
}
__device__ __forceinline__ void cp_commit() { asm volatile("cp.async.commit_group;"); }
template <int N> __device__ __forceinline__ void cp_wait() {
    asm volatile("cp.async.wait_group %0;" :: "n"(N));
}

// ================= WIDE chain GEMM: 128x128x32, 8 warps @ 64x32 tiles =================
// C_rows = idx[0..*cnt): x[r,:] += gate[r]*(xr[r,:] @ T^T) in place; writes next rounded buf.
// 1-term tf32, operands pre-rounded. 2 CTAs/SM (regs<=128, smem 73.7KB).
constexpr int WLD = 36;                         // 32 + 4 pad
constexpr int WTSZ = 128 * WLD;                 // one 128x32 tile in floats
constexpr int WSTAGE = 2 * WTSZ;                // A + B per stage

__global__ void __launch_bounds__(256, 2) gemm_chain(
    const float* __restrict__ A,                // rounded x  [BATCH, FDIM]
    const float* __restrict__ Bm,               // T^T tf32   [FDIM, FDIM] ([N,K])
    float* C,                                   // fp32 x, in-place
    const float* __restrict__ gate, int gcol,
    float* __restrict__ Cr,                     // next rounded buffer
    const int* __restrict__ idx, const int* __restrict__ cnt)
{
    extern __shared__ float smem[];
    __shared__ int sidx[128];

    const int tid = threadIdx.x;
    const int m0 = blockIdx.y * 128;
    const int n0 = blockIdx.x * 128;
    const int warp = tid >> 5;
    const int wm = warp >> 2;      // 0..1 -> 64-row slice
    const int wn = warp & 3;       // 0..3 -> 32-col slice

    const int n_act = *cnt;
    if (m0 >= n_act) return;
    if (tid < 128) {
        int m = m0 + tid;
        sidx[tid] = (m < n_act) ? idx[m] : idx[m0];
    }
    __syncthreads();

    wmma::fragment<wmma::accumulator, 16, 16, 8, float> acc[4][2];
#pragma unroll
    for (int i = 0; i < 4; i++)
#pragma unroll
        for (int j = 0; j < 2; j++) wmma::fill_fragment(acc[i][j], 0.0f);

    auto load_stage = [&](int s, int k0) {
        float* as = smem + s * WSTAGE;
        float* bs = as + WTSZ;
#pragma unroll
        for (int i = 0; i < 4; i++) {
            int e = i * 256 + tid;
            int r = e >> 3, c = (e & 7) << 2;
            cp16(&as[r * WLD + c], &A[(size_t)sidx[r] * FDIM + k0 + c]);
        }
#pragma unroll
        for (int i = 0; i < 4; i++) {
            int e = i * 256 + tid;
            int r = e >> 3, c = (e & 7) << 2;
            cp16(&bs[r * WLD + c], &Bm[(size_t)(n0 + r) * FDIM + k0 + c]);
        }
    };

    load_stage(0, 0);
    cp_commit();

    constexpr int ITERS = FDIM / 32;
    for (int it = 0; it < ITERS; it++) {
        if (it + 1 < ITERS) load_stage((it + 1) & 1, (it + 1) * 32);
        cp_commit();              // empty group on last iter keeps counts aligned
        cp_wait<1>();
        __syncthreads();

        const float* as = smem + (it & 1) * WSTAGE;
        const float* bs = as + WTSZ;

#pragma unroll
        for (int kk = 0; kk < 4; kk++) {
            wmma::fragment<wmma::matrix_a, 16, 16, 8, wmma::precision::tf32, wmma::row_major> af[4];
            wmma::fragment<wmma::matrix_b, 16, 16, 8, wmma::precision::tf32, wmma::col_major> bf[2];
#pragma unroll
            for (int i = 0; i < 4; i++)
                wmma::load_matrix_sync(af[i], &as[(wm * 64 + i * 16) * WLD + kk * 8], WLD);
#pragma unroll
            for (int j = 0; j < 2; j++)
                wmma::load_matrix_sync(bf[j], &bs[(wn * 32 + j * 16) * WLD + kk * 8], WLD);
#pragma unroll
            for (int i = 0; i < 4; i++)
#pragma unroll
                for (int j = 0; j < 2; j++)
                    wmma::mma_sync(acc[i][j], af[i], bf[j], acc[i][j]);
        }
        __syncthreads();
    }

    // epilogue: stage to smem (reuse pipeline buffers), gated in-place update
    constexpr int SLD = 132;
    float* St = smem;
#pragma unroll
    for (int i = 0; i < 4; i++)
#pragma unroll
        for (int j = 0; j < 2; j++)
            wmma::store_matrix_sync(&St[(wm * 64 + i * 16) * SLD + wn * 32 + j * 16],
                                    acc[i][j], SLD, wmma::mem_row_major);
    __syncthreads();
#pragma unroll
    for (int it = 0; it < 16; it++) {
        int e = it * 256 + tid;
        int r = e >> 5, c = (e & 31) << 2;
        if (m0 + r >= n_act) continue;
        int grow = sidx[r];
        size_t ix = (size_t)grow * FDIM + n0 + c;
        float g = gate[grow * NTASK + gcol];
        float4 v = *(const float4*)&St[r * SLD + c];
        float4 rs = *(const float4*)&C[ix];
        v.x = rs.x + g * v.x; v.y = rs.y + g * v.y;
        v.z = rs.z + g * v.z; v.w = rs.w + g * v.w;
        *(float4*)&C[ix] = v;
        float4 t;
        t.x = wmma::__float_to_tf32(v.x); t.y = wmma::__float_to_tf32(v.y);
        t.z = wmma::__float_to_tf32(v.z); t.w = wmma::__float_to_tf32(v.w);
        *(float4*)&Cr[ix] = t;
    }
}

// ================= narrow GEMM (h 3-term split-K, proj fallback) =================
constexpr int BM = 128, BN = 64;

template <int BKT, bool THREE, int EPI, bool GATHER>
__global__ void __launch_bounds__(256, 2) gemm_tf32(
    const float* __restrict__ A, const float* __restrict__ Alo, int lda,
    const float* __restrict__ Bm, const float* __restrict__ Blo, int ldb,
    float* C, int ldc, int Kdim, int zstride,
    const float* resid,
    const float* __restrict__ gate, int gcol,
    float* __restrict__ Cr,
    const int* __restrict__ idx, const int* __restrict__ cnt)
{
    constexpr int ALD = BKT + 4;
    constexpr int ASZ = BM * ALD;
    constexpr int BSZ = BN * ALD;
    constexpr int NTA = THREE ? 2 : 1;
    constexpr int STAGE = NTA * (ASZ + BSZ);
    constexpr int AQ = BKT / 4;
    constexpr int AIT = BM * AQ / 256;
    constexpr int BIT = BN * AQ / 256;

    extern __shared__ float smem[];
    __shared__ int sidx[BM];

    const int tid = threadIdx.x;
    const int m0 = blockIdx.y * BM;
    const int n0 = blockIdx.x * BN;
    const int warp = tid >> 5;
    const int wm = warp >> 1;
    const int wn = warp & 1;
    const int koff = blockIdx.z * Kdim;

    if (EPI == 5) {
        if (g_notident == 0u) {    // proj == identity: copy resid tile
#pragma unroll
            for (int it = 0; it < 8; it++) {
                int e = it * 256 + tid;
                int r = e >> 4, c = (e & 15) << 2;
                size_t ix = (size_t)(m0 + r) * ldc + n0 + c;
                *(float4*)&C[ix] = *(const float4*)&resid[ix];
            }
            return;
        }
    }

    int n_act = 0;
    if (GATHER) {
        n_act = *cnt;
        if (m0 >= n_act) return;
        int m = m0 + tid;
        if (tid < BM) sidx[tid] = (m < n_act) ? idx[m] : idx[m0];
        __syncthreads();
    }

    wmma::fragment<wmma::accumulator, 16, 16, 8, float> acc[2][2];
#pragma unroll
    for (int i = 0; i < 2; i++)
#pragma unroll
        for (int j = 0; j < 2; j++) wmma::fill_fragment(acc[i][j], 0.0f);

    const int iters = Kdim / BKT;

    auto load_stage = [&](int s, int k0) {
        float* as = smem + s * STAGE;
        float* al = as + ASZ;
        float* bs = as + NTA * ASZ;
        float* bl = bs + BSZ;
#pragma unroll
        for (int i = 0; i < AIT; i++) {
            int e = i * 256 + tid;
            int r = e / AQ, c = (e % AQ) << 2;
            int grow = GATHER ? sidx[r] : (m0 + r);
            cp16(&as[r * ALD + c], &A[(size_t)grow * lda + koff + k0 + c]);
            if (THREE) cp16(&al[r * ALD + c], &Alo[(size_t)grow * lda + koff + k0 + c]);
        }
#pragma unroll
        for (int i = 0; i < BIT; i++) {
            int e = i * 256 + tid;
            int r = e / AQ, c = (e % AQ) << 2;
            cp16(&bs[r * ALD + c], &Bm[(size_t)(n0 + r) * ldb + koff + k0 + c]);
            if (THREE) cp16(&bl[r * ALD + c], &Blo[(size_t)(n0 + r) * ldb + koff + k0 + c]);
        }
    };

    load_stage(0, 0);
    cp_commit();

    for (int it = 0; it < iters; it++) {
        if (it + 1 < iters) load_stage((it + 1) & 1, (it + 1) * BKT);
        cp_commit();
        cp_wait<1>();
        __syncthreads();

        const float* as = smem + (it & 1) * STAGE;
        const float* al = as + ASZ;
        const float* bs = as + NTA * ASZ;
        const float* bl = bs + BSZ;

#pragma unroll
        for (int kk = 0; kk < BKT / 8; kk++) {
            wmma::fragment<wmma::matrix_a, 16, 16, 8, wmma::precision::tf32, wmma::row_major> af[2], afl[THREE ? 2 : 1];
            wmma::fragment<wmma::matrix_b, 16, 16, 8, wmma::precision::tf32, wmma::col_major> bf[2], bfl[THREE ? 2 : 1];
#pragma unroll
            for (int i = 0; i < 2; i++) {
                wmma::load_matrix_sync(af[i], &as[(wm * 32 + i * 16) * ALD + kk * 8], ALD);
                if (THREE)
                    wmma::load_matrix_sync(afl[i], &al[(wm * 32 + i * 16) * ALD + kk * 8], ALD);
            }
#pragma unroll
            for (int j = 0; j < 2; j++) {
                wmma::load_matrix_sync(bf[j], &bs[(wn * 32 + j * 16) * ALD + kk * 8], ALD);
                if (THREE)
                    wmma::load_matrix_sync(bfl[j], &bl[(wn * 32 + j * 16) * ALD + kk * 8], ALD);
            }
#pragma unroll
            for (int i = 0; i < 2; i++)
#pragma unroll
                for (int j = 0; j < 2; j++) {
                    if (THREE) {
                        wmma::mma_sync(acc[i][j], af[i], bfl[j], acc[i][j]);
                        wmma::mma_sync(acc[i][j], afl[i], bf[j], acc[i][j]);
                    }
                    wmma::mma_sync(acc[i][j], af[i], bf[j], acc[i][j]);
                }
        }
        __syncthreads();
    }

    constexpr int SLD = BN + 4;
    float* St = smem;
#pragma unroll
    for (int i = 0; i < 2; i++)
#pragma unroll
        for (int j = 0; j < 2; j++)
            wmma::store_matrix_sync(&St[(wm * 32 + i * 16) * SLD + wn * 32 + j * 16],
                                    acc[i][j], SLD, wmma::mem_row_major);
    __syncthreads();
#pragma unroll
    for (int it = 0; it < 8; it++) {
        int e = it * 256 + tid;
        int r = e >> 4, c = (e & 15) << 2;
        float4 v = *(const float4*)&St[r * SLD + c];
        int col = n0 + c;
        if (EPI == 3) {
            if (m0 + r >= n_act) continue;
            int grow = sidx[r];
            size_t ix = (size_t)grow * ldc + col;
            float g = gate[grow * NTASK + gcol];
            float4 rs = *(const float4*)&resid[ix];
            v.x = rs.x + g * v.x; v.y = rs.y + g * v.y;
            v.z = rs.z + g * v.z; v.w = rs.w + g * v.w;
            *(float4*)&C[ix] = v;
            float4 t;
            t.x = wmma::__float_to_tf32(v.x); t.y = wmma::__float_to_tf32(v.y);
            t.z = wmma::__float_to_tf32(v.z); t.w = wmma::__float_to_tf32(v.w);
            *(float4*)&Cr[ix] = t;
        } else {
            size_t ix = (size_t)blockIdx.z * zstride + (size_t)(m0 + r) * ldc + col;
            *(float4*)&C[ix] = v;
        }
    }
}

// ---------------- G = W1 @ W1^T in exact fp32 (SIMT, smem-tiled) ----------------
__global__ void __launch_bounds__(256) gram_kernel(const float* __restrict__ W1)
{
    __shared__ float As[32][33], Bs[32][33];
    const int tid = threadIdx.x;
    const int r0 = blockIdx.y * 32, c0 = blockIdx.x * 32;
    const int ty = tid >> 4, tx = tid & 15;
    float a00 = 0.f, a01 = 0.f, a10 = 0.f, a11 = 0.f;

    for (int k0 = 0; k0 < FDIM; k0 += 32) {
#pragma unroll
        for (int i = 0; i < 4; i++) {
            int e = i * 256 + tid;
            int r = e >> 5, c = e & 31;
            As[r][c] = W1[(size_t)(r0 + r) * FDIM + k0 + c];
            Bs[r][c] = W1[(size_t)(c0 + r) * FDIM + k0 + c];
        }
        __syncthreads();
#pragma unroll 8
        for (int k = 0; k < 32; k++) {
            float x0 = As[ty * 2][k],     x1 = As[ty * 2 + 1][k];
            float y0 = Bs[tx * 2][k],     y1 = Bs[tx * 2 + 1][k];
            a00 = fmaf(x0, y0, a00); a01 = fmaf(x0, y1, a01);
            a10 = fmaf(x1, y0, a10); a11 = fmaf(x1, y1, a11);
        }
        __syncthreads();
    }
    int gr = r0 + ty * 2, gc = c0 + tx * 2;
    g_G[gr * HDIM + gc] = a00;       g_G[gr * HDIM + gc + 1] = a01;
    g_G[(gr + 1) * HDIM + gc] = a10; g_G[(gr + 1) * HDIM + gc + 1] = a11;
}

// ---------------- h reduce ----------------
__global__ void __launch_bounds__(256) hreduce_kernel(const float* __restrict__ b1)
{
    int e = blockIdx.x * 256 + threadIdx.x;
    size_t ix = (size_t)e * 4;
    int col = (int)(ix & (HDIM - 1));
    float4 p0 = *(const float4*)&g_hpart[ix];
    float4 p1 = *(const float4*)&g_hpart[(size_t)BATCH * HDIM + ix];
    float4 v;
    v.x = p0.x + p1.x + b1[col];
    v.y = p0.y + p1.y + b1[col + 1];
    v.z = p0.z + p1.z + b1[col + 2];
    v.w = p0.w + p1.w + b1[col + 3];
    *(float4*)&g_h[ix] = v;
}

// ---------------- prep ----------------
__global__ void __launch_bounds__(256) prep_kernel(
    const float* __restrict__ F, const float* __restrict__ T,
    const float* __restrict__ W1, const float* __restrict__ P)
{
    int b = blockIdx.x, tid = threadIdx.x;
    if (b < 8192) {
        __shared__ float s[32][33];
        int j = b >> 10, t = b & 1023;
        int tr = t >> 5, tc = t & 31;
        int x = tid & 31, y = tid >> 5;
        const float* src = T + (size_t)j * FDIM * FDIM;
#pragma unroll
        for (int i = 0; i < 4; i++)
            s[y + i * 8][x] = src[(size_t)(tr * 32 + y + i * 8) * FDIM + tc * 32 + x];
        __syncthreads();
        float* dh = g_Thi + (size_t)j * FDIM * FDIM;
#pragma unroll
        for (int i = 0; i < 4; i++) {
            int n = tc * 32 + y + i * 8, k = tr * 32 + x;
            dh[(size_t)n * FDIM + k] = wmma::__float_to_tf32(s[x][y + i * 8]);
        }
    } else if (b < 10240) {
        size_t base = (size_t)(b - 8192) * 4096 + tid * 16;
#pragma unroll
        for (int q = 0; q < 4; q++) {
            float4 v = *(const float4*)&F[base + q * 4];
            *(float4*)&g_xa[base + q * 4] = v;
            float vv[4] = {v.x, v.y, v.z, v.w};
#pragma unroll
            for (int e = 0; e < 4; e++) {
                size_t ix = base + q * 4 + e;
                float hi = wmma::__float_to_tf32(vv[e]);
                g_fhi[ix] = hi;
                g_flo[ix] = wmma::__float_to_tf32(vv[e] - hi);
            }
        }
    } else if (b < 10304) {
        size_t base = (size_t)(b - 10240) * 4096 + tid * 16;
#pragma unroll
        for (int q = 0; q < 4; q++) {
            float4 v = *(const float4*)&W1[base + q * 4];
            float vv[4] = {v.x, v.y, v.z, v.w};
#pragma unroll
            for (int e = 0; e < 4; e++) {
                size_t ix = base + q * 4 + e;
                float hi = wmma::__float_to_tf32(vv[e]);
                g_W1hi[ix] = hi;
                g_W1lo[ix] = wmma::__float_to_tf32(vv[e] - hi);
            }
        }
    } else {
        size_t base = (size_t)(b - 10304) * 4096 + tid * 16;
#pragma unroll
        for (int q = 0; q < 4; q++) {
            float4 v = *(const float4*)&P[base + q * 4];
            float vv[4] = {v.x, v.y, v.z, v.w};
#pragma unroll
            for (int e = 0; e < 4; e++) {
                size_t ix = base + q * 4 + e;
                float hi = wmma::__float_to_tf32(vv[e]);
                g_Phi[ix] = hi;
                g_Plo[ix] = wmma::__float_to_tf32(vv[e] - hi);
            }
        }
    }
}

// ---------------- proj identity check ----------------
__global__ void projchk_kernel(const float* __restrict__ P)
{
    int e = blockIdx.x * 256 + threadIdx.x;
    int idx4 = e * 4;
    int row = idx4 >> 10;
    float4 v = *(const float4*)&P[idx4];
    float vv[4] = {v.x, v.y, v.z, v.w};
    bool bad = false;
#pragma unroll
    for (int q = 0; q < 4; q++) {
        int col = (idx4 + q) & 1023;
        float exp = (col == row) ? 1.0f : 0.0f;
        if (vv[q] != exp) bad = true;
    }
    if (__syncthreads_or(bad) && threadIdx.x == 0) atomicOr(&g_notident, 1u);
}

// ---------------- split final x (only if proj != I) ----------------
__global__ void __launch_bounds__(256) splitx_kernel(const float* __restrict__ X)
{
    if (g_notident == 0u) return;
    size_t base = (size_t)blockIdx.x * 4096 + threadIdx.x * 16;
#pragma unroll
    for (int q = 0; q < 4; q++) {
        float4 v = *(const float4*)&X[base + q * 4];
        float vv[4] = {v.x, v.y, v.z, v.w};
#pragma unroll
        for (int e = 0; e < 4; e++) {
            size_t ix = base + q * 4 + e;
            float hi = wmma::__float_to_tf32(vv[e]);
            g_fhi[ix] = hi;
            g_flo[ix] = wmma::__float_to_tf32(vv[e] - hi);
        }
    }
}

// ---------------- coeffs ----------------
__global__ void coeffs_kernel(const float* __restrict__ W2, const float* __restrict__ b2)
{
    int tid = threadIdx.x;
    int row = blockIdx.x * 32 + (tid >> 3);
    int k = tid & 7;
    const float* hr = g_h + (size_t)row * HDIM;
    const float* w = W2 + k * HDIM;
    float s = b2[k];
#pragma unroll 8
    for (int h = 0; h < HDIM; h++) s += fmaxf(hr[h], 0.0f) * w[h];
    g_coeffs[row * NTASK + k] = s;
}

// ---------------- unc ----------------
__global__ void __launch_bounds__(256) unc_kernel(const float* __restrict__ W2)
{
    __shared__ float W2s[NTASK * HDIM];
    __shared__ float Gs[HDIM * 32];
    int tid = threadIdx.x, lane = tid & 31, warp = tid >> 5;
    for (int i = tid; i < NTASK * HDIM; i += 256) W2s[i] = W2[i];

    int row = blockIdx.x * 8 + warp;
    const float* hr = g_h + (size_t)row * HDIM;
    unsigned mb[8];
#pragma unroll
    for (int j = 0; j < 8; j++)
        mb[j] = __ballot_sync(0xffffffffu, hr[j * 32 + lane] > 0.0f);

    float u2[8];
#pragma unroll
    for (int k = 0; k < 8; k++) u2[k] = 0.0f;

    for (int c = 0; c < 8; c++) {
        __syncthreads();
        for (int i = tid; i < HDIM * 32; i += 256) {
            int h = i >> 5, l = i & 31;
            Gs[i] = g_G[h * HDIM + c * 32 + l];
        }
        __syncthreads();
        float t[8];
#pragma unroll
        for (int k = 0; k < 8; k++) t[k] = 0.0f;
        for (int h = 0; h < HDIM; h++) {
            if ((mb[h >> 5] >> (h & 31)) & 1u) {
                float gv = Gs[h * 32 + lane];
#pragma unroll
                for (int k = 0; k < 8; k++) t[k] += W2s[k * HDIM + h] * gv;
            }
        }
        int hp = c * 32 + lane;
        if ((mb[hp >> 5] >> (hp & 31)) & 1u) {
#pragma unroll
            for (int k = 0; k < 8; k++) u2[k] += W2s[k * HDIM + hp] * t[k];
        }
    }
#pragma unroll
    for (int k = 0; k < 8; k++) {
        float v = u2[k];
        for (int off = 16; off; off >>= 1) v += __shfl_down_sync(0xffffffffu, v, off);
        if (lane == 0) {
            v = fmaxf(v, 0.0f);
            g_unc2[row * NTASK + k] = v;
            atomicMax(&g_max2bits, __float_as_uint(v));
        }
    }
}

// ---------------- gating + compaction ----------------
__global__ void gate_kernel(const float* __restrict__ bthr, const float* __restrict__ beta)
{
    int i = blockIdx.x * blockDim.x + threadIdx.x;
    if (i >= BATCH * NTASK) return;
    int row = i >> 3, k = i & 7;
    float max2 = __uint_as_float(g_max2bits);
    float u = (max2 > 0.0f) ? sqrtf(g_unc2[i] / max2) : sqrtf(g_unc2[i]);
    float base = log1pf(expf(bthr[0]));
    float thr = base * (1.0f + fmaxf(beta[0], 0.0f) * u);
    float cf = g_coeffs[i];
    float gf = (fabsf(cf) < thr) ? 0.0f : cf;
    g_gated[i] = gf;
    if (gf != 0.0f) {
        int p = atomicAdd(&g_cnt[k], 1);
        g_idx[k * BATCH + p] = row;
    }
}

// ---------------- copy rounded buffer for zero-gate rows ----------------
__global__ void __launch_bounds__(256) copy_round_inactive(
    const float* __restrict__ rin, float* __restrict__ rout, int j)
{
    int row = blockIdx.x;
    if (g_gated[row * NTASK + j] != 0.0f) return;
    size_t b4 = (size_t)row * (FDIM / 4) + threadIdx.x;
    ((float4*)rout)[b4] = ((const float4*)rin)[b4];
}

// ---------------- launch ----------------
extern "C" void kernel_launch(void* const* d_in, const int* in_sizes, int n_in,
                              void* d_out, int out_size)
{
    const float* features = (const float*)d_in[0];
    const float* W1   = (const float*)d_in[1];
    const float* b1   = (const float*)d_in[2];
    const float* W2   = (const float*)d_in[3];
    const float* b2   = (const float*)d_in[4];
    const float* task = (const float*)d_in[5];
    const float* projW = (const float*)d_in[6];
    const float* bthr = (const float*)d_in[7];
    const float* beta = (const float*)d_in[8];
    float* out = (float*)d_out;

    float *fhi, *flo, *w1hi, *w1lo, *thi, *phi, *plo;
    float *xa, *xar, *xbr, *hpart, *gated;
    int *idxp, *cntp;
    void *maxp, *nip;
    cudaGetSymbolAddress((void**)&fhi, g_fhi);   cudaGetSymbolAddress((void**)&flo, g_flo);
    cudaGetSymbolAddress((void**)&w1hi, g_W1hi); cudaGetSymbolAddress((void**)&w1lo, g_W1lo);
    cudaGetSymbolAddress((void**)&thi, g_Thi);
    cudaGetSymbolAddress((void**)&phi, g_Phi);   cudaGetSymbolAddress((void**)&plo, g_Plo);
    cudaGetSymbolAddress((void**)&xa, g_xa);
    cudaGetSymbolAddress((void**)&xar, g_xar);   cudaGetSymbolAddress((void**)&xbr, g_xbr);
    cudaGetSymbolAddress((void**)&hpart, g_hpart);
    cudaGetSymbolAddress((void**)&gated, g_gated);
    cudaGetSymbolAddress((void**)&idxp, g_idx);  cudaGetSymbolAddress((void**)&cntp, g_cnt);
    cudaGetSymbolAddress(&maxp, g_max2bits);     cudaGetSymbolAddress(&nip, g_notident);

    const int smem_h  = 2 * 2 * (BM * 20 + BN * 20) * 4;      // 61440
    const int smem_p  = 2 * 2 * (BM * 36 + BN * 36) * 4;      // 110592
    const int smem_w  = 2 * WSTAGE * 4;                       // 73728
    cudaFuncSetAttribute(gemm_tf32<16, true,  0, false>, cudaFuncAttributeMaxDynamicSharedMemorySize, smem_h);
    cudaFuncSetAttribute(gemm_tf32<32, true,  5, false>, cudaFuncAttributeMaxDynamicSharedMemorySize, smem_p);
    cudaFuncSetAttribute(gemm_chain, cudaFuncAttributeMaxDynamicSharedMemorySize, smem_w);

    cudaMemsetAsync(maxp, 0, 4);
    cudaMemsetAsync(cntp, 0, NTASK * sizeof(int));
    cudaMemsetAsync(nip, 0, 4);

    // (1) prep (+x init) and proj identity check
    prep_kernel<<<10560, 256>>>(features, task, W1, projW);
    projchk_kernel<<<1024, 256>>>(projW);

    // (2) G exact fp32
    gram_kernel<<<dim3(8, 8), 256>>>(W1);

    // (3) h: split-K=2, 3-term tf32, BK=16
    gemm_tf32<16, true, 0, false><<<dim3(HDIM / BN, BATCH / BM, 2), 256, smem_h>>>(
        fhi, flo, FDIM, w1hi, w1lo, FDIM, hpart, HDIM, FDIM / 2, BATCH * HDIM,
        nullptr, nullptr, 0, nullptr, nullptr, nullptr);
    hreduce_kernel<<<BATCH * HDIM / 1024, 256>>>(b1);

    // (4-6) coeffs, unc, gate+compact
    coeffs_kernel<<<BATCH / 32, 256>>>(W2, b2);
    unc_kernel<<<BATCH / 8, 256>>>(W2);
    gate_kernel<<<(BATCH * NTASK + 255) / 256, 256>>>(bthr, beta);

    // (7..) chain: wide gathered GEMM, in-place fp32 x, rounded ping-pong
    dim3 gW(FDIM / 128, BATCH / 128);    // 8 x 64
    const float* around = fhi;
    float* nextr = xar;
    for (int j = 0; j < NTASK; j++) {
        copy_round_inactive<<<BATCH, 256>>>(around, nextr, j);
        gemm_chain<<<gW, 256, smem_w>>>(
            around, thi + (size_t)j * FDIM * FDIM, xa, gated, j, nextr,
            idxp + j * BATCH, cntp + j);
        around = nextr;
        nextr = (around == xar) ? xbr : xar;
    }

    // final split (no-op when proj == I)
    splitx_kernel<<<BATCH * FDIM / 4096, 256>>>(xa);

    // proj: identity -> copy, else 3-term GEMM
    gemm_tf32<32, true, 5, false><<<dim3(FDIM / BN, BATCH / BM), 256, smem_p>>>(
        fhi, flo, FDIM, phi, plo, FDIM, out, FDIM, FDIM, 0,
        xa, nullptr, 0, nullptr, nullptr, nullptr);
}

// round 13
// speedup vs baseline: 2.0315x; 2.0315x over previous
#include <cuda_runtime.h>
#include <mma.h>
#include <cstdint>
#include <cstddef>

using namespace nvcuda;

#define BATCH 8192
#define FDIM  1024
#define HDIM  256
#define NTASK 8

// ---------------- scratch (static device globals; no allocation) ----------------
__device__ float g_fhi[BATCH * FDIM], g_flo[BATCH * FDIM];   // features tf32 split; reused for final-x split
__device__ float g_W1hi[HDIM * FDIM], g_W1lo[HDIM * FDIM];
__device__ float g_Thi[NTASK * FDIM * FDIM];                 // task mats transposed to [N,K], tf32
__device__ float g_Phi[FDIM * FDIM], g_Plo[FDIM * FDIM];     // projW split ([N,K] layout already)
__device__ float g_xa[BATCH * FDIM];                         // chain x, updated IN PLACE
__device__ float g_xar[BATCH * FDIM], g_xbr[BATCH * FDIM];   // tf32-rounded x ping-pong (A operand)
__device__ float g_hpart[2 * BATCH * HDIM];                  // h split-K partials
__device__ float    g_h[BATCH * HDIM];
__device__ float    g_G[HDIM * HDIM];
__device__ float    g_coeffs[BATCH * NTASK];
__device__ float    g_unc2[BATCH * NTASK];
__device__ unsigned g_max2bits;
__device__ float    g_gated[BATCH * NTASK];
__device__ int      g_cnt[NTASK];
__device__ int      g_idx[NTASK * BATCH];
__device__ unsigned g_notident;

// ---------------- cp.async helpers ----------------
__device__ __forceinline__ void cp16(float* s, const float* g) {
    unsigned sa = (unsigned)__cvta_generic_to_shared(s);
    asm volatile("cp.async.cg.shared.global [%0], [%1], 16;" :: "r"(sa), "l"(g));
}
__device__ __forceinline__ void cp_commit() { asm volatile("cp.async.commit_group;"); }
template <int N> __device__ __forceinline__ void cp_wait() {
    asm volatile("cp.async.wait_group %0;" :: "n"(N));
}

// ---------------- manual mma helpers ----------------
__device__ __forceinline__ void ldsm4(uint32_t& r0, uint32_t& r1, uint32_t& r2, uint32_t& r3,
                                      uint32_t addr) {
    asm volatile("ldmatrix.sync.aligned.m8n8.x4.shared.b16 {%0,%1,%2,%3}, [%4];"
        : "=r"(r0), "=r"(r1), "=r"(r2), "=r"(r3) : "r"(addr));
}
__device__ __forceinline__ void mma_tf32(float* d, const uint32_t* a, const uint32_t* b) {
    asm volatile("mma.sync.aligned.m16n8k8.row.col.f32.tf32.tf32.f32 "
        "{%0,%1,%2,%3}, {%4,%5,%6,%7}, {%8,%9}, {%0,%1,%2,%3};"
        : "+f"(d[0]), "+f"(d[1]), "+f"(d[2]), "+f"(d[3])
        : "r"(a[0]), "r"(a[1]), "r"(a[2]), "r"(a[3]), "r"(b[0]), "r"(b[1]));
}

// ================= chain GEMM: 128x64x32, 8 warps @ 32x32, manual mma + ldmatrix =================
constexpr int CLD = 36;                          // 32 + 4 pad (floats)
constexpr int CASZ = 128 * CLD;
constexpr int CBSZ = 64 * CLD;
constexpr int CSTAGE = CASZ + CBSZ;

__global__ void __launch_bounds__(256, 2) gemm_chain(
    const float* __restrict__ A,                // rounded x  [BATCH, FDIM]
    const float* __restrict__ Bm,               // T^T tf32   [FDIM, FDIM] ([N,K])
    float* C,                                   // fp32 x, in-place
    const float* __restrict__ gate, int gcol,
    float* __restrict__ Cr,                     // next rounded buffer
    const int* __restrict__ idx, const int* __restrict__ cnt)
{
    extern __shared__ float smem[];
    __shared__ int sidx[128];

    const int tid = threadIdx.x;
    const int lane = tid & 31;
    const int warp = tid >> 5;
    const int m0 = blockIdx.y * 128;
    const int n0 = blockIdx.x * 64;
    const int wm0 = (warp >> 1) * 32;            // 0..3 -> 32-row slice
    const int wn0 = (warp & 1) * 32;             // 0..1 -> 32-col slice

    const int n_act = *cnt;
    if (m0 >= n_act) return;
    if (tid < 128) {
        int m = m0 + tid;
        sidx[tid] = (m < n_act) ? idx[m] : idx[m0];
    }
    __syncthreads();

    float acc[2][4][4];
#pragma unroll
    for (int mi = 0; mi < 2; mi++)
#pragma unroll
        for (int nj = 0; nj < 4; nj++)
#pragma unroll
            for (int c = 0; c < 4; c++) acc[mi][nj][c] = 0.0f;

    auto load_stage = [&](int s, int k0) {
        float* as = smem + s * CSTAGE;
        float* bs = as + CASZ;
#pragma unroll
        for (int i = 0; i < 4; i++) {
            int e = i * 256 + tid;
            int r = e >> 3, c = (e & 7) << 2;
            cp16(&as[r * CLD + c], &A[(size_t)sidx[r] * FDIM + k0 + c]);
        }
#pragma unroll
        for (int i = 0; i < 2; i++) {
            int e = i * 256 + tid;
            int r = e >> 3, c = (e & 7) << 2;
            cp16(&bs[r * CLD + c], &Bm[(size_t)(n0 + r) * FDIM + k0 + c]);
        }
    };

    load_stage(0, 0);
    cp_commit();

    const uint32_t smb = (uint32_t)__cvta_generic_to_shared(smem);
    // ldmatrix lane address components (fragment-exact, derived from mma layouts):
    // A x4: rows wm0 + (lane&15), col (lane>>4)*4     -> regs a0..a3 of m16k8 tile
    // B x4: rows wn0 + (lane&7) + ((lane>>4)<<3), col ((lane>>3)&1)*4 -> b0,b1 of two n8 tiles
    const uint32_t aoff = ((wm0 + (lane & 15)) * CLD + ((lane >> 4) << 2)) * 4;
    const uint32_t boff = (CASZ + ((wn0 + (lane & 7) + ((lane >> 4) << 3)) * CLD
                          + (((lane >> 3) & 1) << 2))) * 4;

    constexpr int ITERS = FDIM / 32;
    for (int it = 0; it < ITERS; it++) {
        if (it + 1 < ITERS) load_stage((it + 1) & 1, (it + 1) * 32);
        cp_commit();              // empty group on last iter keeps counts aligned
        cp_wait<1>();
        __syncthreads();

        const uint32_t sa = smb + (uint32_t)((it & 1) * CSTAGE) * 4;
        const uint32_t aaddr  = sa + aoff;
        const uint32_t aaddr2 = aaddr + 16 * CLD * 4;
        const uint32_t baddr  = sa + boff;
        const uint32_t baddr2 = baddr + 16 * CLD * 4;

#pragma unroll
        for (int kk = 0; kk < 4; kk++) {
            uint32_t a[2][4], b[4][2];
            ldsm4(a[0][0], a[0][1], a[0][2], a[0][3], aaddr  + kk * 32);
            ldsm4(a[1][0], a[1][1], a[1][2], a[1][3], aaddr2 + kk * 32);
            ldsm4(b[0][0], b[0][1], b[1][0], b[1][1], baddr  + kk * 32);
            ldsm4(b[2][0], b[2][1], b[3][0], b[3][1], baddr2 + kk * 32);
#pragma unroll
            for (int mi = 0; mi < 2; mi++)
#pragma unroll
                for (int nj = 0; nj < 4; nj++)
                    mma_tf32(acc[mi][nj], a[mi], b[nj]);
        }
        __syncthreads();
    }

    // epilogue: manual fragment store to smem, then gathered gated in-place update
    constexpr int SLD = 68;
    float* St = smem;
#pragma unroll
    for (int mi = 0; mi < 2; mi++)
#pragma unroll
        for (int nj = 0; nj < 4; nj++) {
            int r = wm0 + mi * 16 + (lane >> 2);
            int cc = wn0 + nj * 8 + (lane & 3) * 2;
            St[r * SLD + cc]           = acc[mi][nj][0];
            St[r * SLD + cc + 1]       = acc[mi][nj][1];
            St[(r + 8) * SLD + cc]     = acc[mi][nj][2];
            St[(r + 8) * SLD + cc + 1] = acc[mi][nj][3];
        }
    __syncthreads();
#pragma unroll
    for (int it = 0; it < 8; it++) {
        int e = it * 256 + tid;
        int r = e >> 4, c = (e & 15) << 2;
        if (m0 + r >= n_act) continue;
        int grow = sidx[r];
        size_t ix = (size_t)grow * FDIM + n0 + c;
        float g = gate[grow * NTASK + gcol];
        float4 v = *(const float4*)&St[r * SLD + c];
        float4 rs = *(const float4*)&C[ix];
        v.x = rs.x + g * v.x; v.y = rs.y + g * v.y;
        v.z = rs.z + g * v.z; v.w = rs.w + g * v.w;
        *(float4*)&C[ix] = v;
        float4 t;
        t.x = wmma::__float_to_tf32(v.x); t.y = wmma::__float_to_tf32(v.y);
        t.z = wmma::__float_to_tf32(v.z); t.w = wmma::__float_to_tf32(v.w);
        *(float4*)&Cr[ix] = t;
    }
}

// ================= narrow wmma GEMM (h 3-term split-K, proj fallback) — proven R10 =================
constexpr int BM = 128, BN = 64;

template <int BKT, bool THREE, int EPI>
__global__ void __launch_bounds__(256, 2) gemm_tf32(
    const float* __restrict__ A, const float* __restrict__ Alo, int lda,
    const float* __restrict__ Bm, const float* __restrict__ Blo, int ldb,
    float* C, int ldc, int Kdim, int zstride,
    const float* resid)
{
    constexpr int ALD = BKT + 4;
    constexpr int ASZ = BM * ALD;
    constexpr int BSZ = BN * ALD;
    constexpr int NTA = THREE ? 2 : 1;
    constexpr int STAGE = NTA * (ASZ + BSZ);
    constexpr int AQ = BKT / 4;
    constexpr int AIT = BM * AQ / 256;
    constexpr int BIT = BN * AQ / 256;

    extern __shared__ float smem[];

    const int tid = threadIdx.x;
    const int m0 = blockIdx.y * BM;
    const int n0 = blockIdx.x * BN;
    const int warp = tid >> 5;
    const int wm = warp >> 1;
    const int wn = warp & 1;
    const int koff = blockIdx.z * Kdim;

    if (EPI == 5) {
        if (g_notident == 0u) {    // proj == identity: copy resid tile
#pragma unroll
            for (int it = 0; it < 8; it++) {
                int e = it * 256 + tid;
                int r = e >> 4, c = (e & 15) << 2;
                size_t ix = (size_t)(m0 + r) * ldc + n0 + c;
                *(float4*)&C[ix] = *(const float4*)&resid[ix];
            }
            return;
        }
    }

    wmma::fragment<wmma::accumulator, 16, 16, 8, float> acc[2][2];
#pragma unroll
    for (int i = 0; i < 2; i++)
#pragma unroll
        for (int j = 0; j < 2; j++) wmma::fill_fragment(acc[i][j], 0.0f);

    const int iters = Kdim / BKT;

    auto load_stage = [&](int s, int k0) {
        float* as = smem + s * STAGE;
        float* al = as + ASZ;
        float* bs = as + NTA * ASZ;
        float* bl = bs + BSZ;
#pragma unroll
        for (int i = 0; i < AIT; i++) {
            int e = i * 256 + tid;
            int r = e / AQ, c = (e % AQ) << 2;
            cp16(&as[r * ALD + c], &A[(size_t)(m0 + r) * lda + koff + k0 + c]);
            if (THREE) cp16(&al[r * ALD + c], &Alo[(size_t)(m0 + r) * lda + koff + k0 + c]);
        }
#pragma unroll
        for (int i = 0; i < BIT; i++) {
            int e = i * 256 + tid;
            int r = e / AQ, c = (e % AQ) << 2;
            cp16(&bs[r * ALD + c], &Bm[(size_t)(n0 + r) * ldb + koff + k0 + c]);
            if (THREE) cp16(&bl[r * ALD + c], &Blo[(size_t)(n0 + r) * ldb + koff + k0 + c]);
        }
    };

    load_stage(0, 0);
    cp_commit();

    for (int it = 0; it < iters; it++) {
        if (it + 1 < iters) load_stage((it + 1) & 1, (it + 1) * BKT);
        cp_commit();
        cp_wait<1>();
        __syncthreads();

        const float* as = smem + (it & 1) * STAGE;
        const float* al = as + ASZ;
        const float* bs = as + NTA * ASZ;
        const float* bl = bs + BSZ;

#pragma unroll
        for (int kk = 0; kk < BKT / 8; kk++) {
            wmma::fragment<wmma::matrix_a, 16, 16, 8, wmma::precision::tf32, wmma::row_major> af[2], afl[THREE ? 2 : 1];
            wmma::fragment<wmma::matrix_b, 16, 16, 8, wmma::precision::tf32, wmma::col_major> bf[2], bfl[THREE ? 2 : 1];
#pragma unroll
            for (int i = 0; i < 2; i++) {
                wmma::load_matrix_sync(af[i], &as[(wm * 32 + i * 16) * ALD + kk * 8], ALD);
                if (THREE)
                    wmma::load_matrix_sync(afl[i], &al[(wm * 32 + i * 16) * ALD + kk * 8], ALD);
            }
#pragma unroll
            for (int j = 0; j < 2; j++) {
                wmma::load_matrix_sync(bf[j], &bs[(wn * 32 + j * 16) * ALD + kk * 8], ALD);
                if (THREE)
                    wmma::load_matrix_sync(bfl[j], &bl[(wn * 32 + j * 16) * ALD + kk * 8], ALD);
            }
#pragma unroll
            for (int i = 0; i < 2; i++)
#pragma unroll
                for (int j = 0; j < 2; j++) {
                    if (THREE) {
                        wmma::mma_sync(acc[i][j], af[i], bfl[j], acc[i][j]);
                        wmma::mma_sync(acc[i][j], afl[i], bf[j], acc[i][j]);
                    }
                    wmma::mma_sync(acc[i][j], af[i], bf[j], acc[i][j]);
                }
        }
        __syncthreads();
    }

    constexpr int SLD = BN + 4;
    float* St = smem;
#pragma unroll
    for (int i = 0; i < 2; i++)
#pragma unroll
        for (int j = 0; j < 2; j++)
            wmma::store_matrix_sync(&St[(wm * 32 + i * 16) * SLD + wn * 32 + j * 16],
                                    acc[i][j], SLD, wmma::mem_row_major);
    __syncthreads();
#pragma unroll
    for (int it = 0; it < 8; it++) {
        int e = it * 256 + tid;
        int r = e >> 4, c = (e & 15) << 2;
        float4 v = *(const float4*)&St[r * SLD + c];
        size_t ix = (size_t)blockIdx.z * zstride + (size_t)(m0 + r) * ldc + n0 + c;
        *(float4*)&C[ix] = v;
    }
}

// ---------------- G = W1 @ W1^T in exact fp32 (SIMT, smem-tiled) ----------------
__global__ void __launch_bounds__(256) gram_kernel(const float* __restrict__ W1)
{
    __shared__ float As[32][33], Bs[32][33];
    const int tid = threadIdx.x;
    const int r0 = blockIdx.y * 32, c0 = blockIdx.x * 32;
    const int ty = tid >> 4, tx = tid & 15;
    float a00 = 0.f, a01 = 0.f, a10 = 0.f, a11 = 0.f;

    for (int k0 = 0; k0 < FDIM; k0 += 32) {
#pragma unroll
        for (int i = 0; i < 4; i++) {
            int e = i * 256 + tid;
            int r = e >> 5, c = e & 31;
            As[r][c] = W1[(size_t)(r0 + r) * FDIM + k0 + c];
            Bs[r][c] = W1[(size_t)(c0 + r) * FDIM + k0 + c];
        }
        __syncthreads();
#pragma unroll 8
        for (int k = 0; k < 32; k++) {
            float x0 = As[ty * 2][k],     x1 = As[ty * 2 + 1][k];
            float y0 = Bs[tx * 2][k],     y1 = Bs[tx * 2 + 1][k];
            a00 = fmaf(x0, y0, a00); a01 = fmaf(x0, y1, a01);
            a10 = fmaf(x1, y0, a10); a11 = fmaf(x1, y1, a11);
        }
        __syncthreads();
    }
    int gr = r0 + ty * 2, gc = c0 + tx * 2;
    g_G[gr * HDIM + gc] = a00;       g_G[gr * HDIM + gc + 1] = a01;
    g_G[(gr + 1) * HDIM + gc] = a10; g_G[(gr + 1) * HDIM + gc + 1] = a11;
}

// ---------------- h reduce ----------------
__global__ void __launch_bounds__(256) hreduce_kernel(const float* __restrict__ b1)
{
    int e = blockIdx.x * 256 + threadIdx.x;
    size_t ix = (size_t)e * 4;
    int col = (int)(ix & (HDIM - 1));
    float4 p0 = *(const float4*)&g_hpart[ix];
    float4 p1 = *(const float4*)&g_hpart[(size_t)BATCH * HDIM + ix];
    float4 v;
    v.x = p0.x + p1.x + b1[col];
    v.y = p0.y + p1.y + b1[col + 1];
    v.z = p0.z + p1.z + b1[col + 2];
    v.w = p0.w + p1.w + b1[col + 3];
    *(float4*)&g_h[ix] = v;
}

// ---------------- prep ----------------
__global__ void __launch_bounds__(256) prep_kernel(
    const float* __restrict__ F, const float* __restrict__ T,
    const float* __restrict__ W1, const float* __restrict__ P)
{
    int b = blockIdx.x, tid = threadIdx.x;
    if (b < 8192) {
        __shared__ float s[32][33];
        int j = b >> 10, t = b & 1023;
        int tr = t >> 5, tc = t & 31;
        int x = tid & 31, y = tid >> 5;
        const float* src = T + (size_t)j * FDIM * FDIM;
#pragma unroll
        for (int i = 0; i < 4; i++)
            s[y + i * 8][x] = src[(size_t)(tr * 32 + y + i * 8) * FDIM + tc * 32 + x];
        __syncthreads();
        float* dh = g_Thi + (size_t)j * FDIM * FDIM;
#pragma unroll
        for (int i = 0; i < 4; i++) {
            int n = tc * 32 + y + i * 8, k = tr * 32 + x;
            dh[(size_t)n * FDIM + k] = wmma::__float_to_tf32(s[x][y + i * 8]);
        }
    } else if (b < 10240) {
        size_t base = (size_t)(b - 8192) * 4096 + tid * 16;
#pragma unroll
        for (int q = 0; q < 4; q++) {
            float4 v = *(const float4*)&F[base + q * 4];
            *(float4*)&g_xa[base + q * 4] = v;
            float vv[4] = {v.x, v.y, v.z, v.w};
#pragma unroll
            for (int e = 0; e < 4; e++) {
                size_t ix = base + q * 4 + e;
                float hi = wmma::__float_to_tf32(vv[e]);
                g_fhi[ix] = hi;
                g_flo[ix] = wmma::__float_to_tf32(vv[e] - hi);
            }
        }
    } else if (b < 10304) {
        size_t base = (size_t)(b - 10240) * 4096 + tid * 16;
#pragma unroll
        for (int q = 0; q < 4; q++) {
            float4 v = *(const float4*)&W1[base + q * 4];
            float vv[4] = {v.x, v.y, v.z, v.w};
#pragma unroll
            for (int e = 0; e < 4; e++) {
                size_t ix = base + q * 4 + e;
                float hi = wmma::__float_to_tf32(vv[e]);
                g_W1hi[ix] = hi;
                g_W1lo[ix] = wmma::__float_to_tf32(vv[e] - hi);
            }
        }
    } else {
        size_t base = (size_t)(b - 10304) * 4096 + tid * 16;
#pragma unroll
        for (int q = 0; q < 4; q++) {
            float4 v = *(const float4*)&P[base + q * 4];
            float vv[4] = {v.x, v.y, v.z, v.w};
#pragma unroll
            for (int e = 0; e < 4; e++) {
                size_t ix = base + q * 4 + e;
                float hi = wmma::__float_to_tf32(vv[e]);
                g_Phi[ix] = hi;
                g_Plo[ix] = wmma::__float_to_tf32(vv[e] - hi);
            }
        }
    }
}

// ---------------- proj identity check ----------------
__global__ void projchk_kernel(const float* __restrict__ P)
{
    int e = blockIdx.x * 256 + threadIdx.x;
    int idx4 = e * 4;
    int row = idx4 >> 10;
    float4 v = *(const float4*)&P[idx4];
    float vv[4] = {v.x, v.y, v.z, v.w};
    bool bad = false;
#pragma unroll
    for (int q = 0; q < 4; q++) {
        int col = (idx4 + q) & 1023;
        float exp = (col == row) ? 1.0f : 0.0f;
        if (vv[q] != exp) bad = true;
    }
    if (__syncthreads_or(bad) && threadIdx.x == 0) atomicOr(&g_notident, 1u);
}

// ---------------- split final x (only if proj != I) ----------------
__global__ void __launch_bounds__(256) splitx_kernel(const float* __restrict__ X)
{
    if (g_notident == 0u) return;
    size_t base = (size_t)blockIdx.x * 4096 + threadIdx.x * 16;
#pragma unroll
    for (int q = 0; q < 4; q++) {
        float4 v = *(const float4*)&X[base + q * 4];
        float vv[4] = {v.x, v.y, v.z, v.w};
#pragma unroll
        for (int e = 0; e < 4; e++) {
            size_t ix = base + q * 4 + e;
            float hi = wmma::__float_to_tf32(vv[e]);
            g_fhi[ix] = hi;
            g_flo[ix] = wmma::__float_to_tf32(vv[e] - hi);
        }
    }
}

// ---------------- coeffs ----------------
__global__ void coeffs_kernel(const float* __restrict__ W2, const float* __restrict__ b2)
{
    int tid = threadIdx.x;
    int row = blockIdx.x * 32 + (tid >> 3);
    int k = tid & 7;
    const float* hr = g_h + (size_t)row * HDIM;
    const float* w = W2 + k * HDIM;
    float s = b2[k];
#pragma unroll 8
    for (int h = 0; h < HDIM; h++) s += fmaxf(hr[h], 0.0f) * w[h];
    g_coeffs[row * NTASK + k] = s;
}

// ---------------- unc ----------------
__global__ void __launch_bounds__(256) unc_kernel(const float* __restrict__ W2)
{
    __shared__ float W2s[NTASK * HDIM];
    __shared__ float Gs[HDIM * 32];
    int tid = threadIdx.x, lane = tid & 31, warp = tid >> 5;
    for (int i = tid; i < NTASK * HDIM; i += 256) W2s[i] = W2[i];

    int row = blockIdx.x * 8 + warp;
    const float* hr = g_h + (size_t)row * HDIM;
    unsigned mb[8];
#pragma unroll
    for (int j = 0; j < 8; j++)
        mb[j] = __ballot_sync(0xffffffffu, hr[j * 32 + lane] > 0.0f);

    float u2[8];
#pragma unroll
    for (int k = 0; k < 8; k++) u2[k] = 0.0f;

    for (int c = 0; c < 8; c++) {
        __syncthreads();
        for (int i = tid; i < HDIM * 32; i += 256) {
            int h = i >> 5, l = i & 31;
            Gs[i] = g_G[h * HDIM + c * 32 + l];
        }
        __syncthreads();
        float t[8];
#pragma unroll
        for (int k = 0; k < 8; k++) t[k] = 0.0f;
        for (int h = 0; h < HDIM; h++) {
            if ((mb[h >> 5] >> (h & 31)) & 1u) {
                float gv = Gs[h * 32 + lane];
#pragma unroll
                for (int k = 0; k < 8; k++) t[k] += W2s[k * HDIM + h] * gv;
            }
        }
        int hp = c * 32 + lane;
        if ((mb[hp >> 5] >> (hp & 31)) & 1u) {
#pragma unroll
            for (int k = 0; k < 8; k++) u2[k] += W2s[k * HDIM + hp] * t[k];
        }
    }
#pragma unroll
    for (int k = 0; k < 8; k++) {
        float v = u2[k];
        for (int off = 16; off; off >>= 1) v += __shfl_down_sync(0xffffffffu, v, off);
        if (lane == 0) {
            v = fmaxf(v, 0.0f);
            g_unc2[row * NTASK + k] = v;
            atomicMax(&g_max2bits, __float_as_uint(v));
        }
    }
}

// ---------------- gating + compaction ----------------
__global__ void gate_kernel(const float* __restrict__ bthr, const float* __restrict__ beta)
{
    int i = blockIdx.x * blockDim.x + threadIdx.x;
    if (i >= BATCH * NTASK) return;
    int row = i >> 3, k = i & 7;
    float max2 = __uint_as_float(g_max2bits);
    float u = (max2 > 0.0f) ? sqrtf(g_unc2[i] / max2) : sqrtf(g_unc2[i]);
    float base = log1pf(expf(bthr[0]));
    float thr = base * (1.0f + fmaxf(beta[0], 0.0f) * u);
    float cf = g_coeffs[i];
    float gf = (fabsf(cf) < thr) ? 0.0f : cf;
    g_gated[i] = gf;
    if (gf != 0.0f) {
        int p = atomicAdd(&g_cnt[k], 1);
        g_idx[k * BATCH + p] = row;
    }
}

// ---------------- copy rounded buffer for zero-gate rows ----------------
__global__ void __launch_bounds__(256) copy_round_inactive(
    const float* __restrict__ rin, float* __restrict__ rout, int j)
{
    int row = blockIdx.x;
    if (g_gated[row * NTASK + j] != 0.0f) return;
    size_t b4 = (size_t)row * (FDIM / 4) + threadIdx.x;
    ((float4*)rout)[b4] = ((const float4*)rin)[b4];
}

// ---------------- launch ----------------
extern "C" void kernel_launch(void* const* d_in, const int* in_sizes, int n_in,
                              void* d_out, int out_size)
{
    const float* features = (const float*)d_in[0];
    const float* W1   = (const float*)d_in[1];
    const float* b1   = (const float*)d_in[2];
    const float* W2   = (const float*)d_in[3];
    const float* b2   = (const float*)d_in[4];
    const float* task = (const float*)d_in[5];
    const float* projW = (const float*)d_in[6];
    const float* bthr = (const float*)d_in[7];
    const float* beta = (const float*)d_in[8];
    float* out = (float*)d_out;

    float *fhi, *flo, *w1hi, *w1lo, *thi, *phi, *plo;
    float *xa, *xar, *xbr, *hpart, *gated;
    int *idxp, *cntp;
    void *maxp, *nip;
    cudaGetSymbolAddress((void**)&fhi, g_fhi);   cudaGetSymbolAddress((void**)&flo, g_flo);
    cudaGetSymbolAddress((void**)&w1hi, g_W1hi); cudaGetSymbolAddress((void**)&w1lo, g_W1lo);
    cudaGetSymbolAddress((void**)&thi, g_Thi);
    cudaGetSymbolAddress((void**)&phi, g_Phi);   cudaGetSymbolAddress((void**)&plo, g_Plo);
    cudaGetSymbolAddress((void**)&xa, g_xa);
    cudaGetSymbolAddress((void**)&xar, g_xar);   cudaGetSymbolAddress((void**)&xbr, g_xbr);
    cudaGetSymbolAddress((void**)&hpart, g_hpart);
    cudaGetSymbolAddress((void**)&gated, g_gated);
    cudaGetSymbolAddress((void**)&idxp, g_idx);  cudaGetSymbolAddress((void**)&cntp, g_cnt);
    cudaGetSymbolAddress(&maxp, g_max2bits);     cudaGetSymbolAddress(&nip, g_notident);

    const int smem_h  = 2 * 2 * (BM * 20 + BN * 20) * 4;      // 61440
    const int smem_p  = 2 * 2 * (BM * 36 + BN * 36) * 4;      // 110592
    const int smem_c  = 2 * CSTAGE * 4;                       // 55296
    cudaFuncSetAttribute(gemm_tf32<16, true, 0>, cudaFuncAttributeMaxDynamicSharedMemorySize, smem_h);
    cudaFuncSetAttribute(gemm_tf32<32, true, 5>, cudaFuncAttributeMaxDynamicSharedMemorySize, smem_p);
    cudaFuncSetAttribute(gemm_chain, cudaFuncAttributeMaxDynamicSharedMemorySize, smem_c);

    cudaMemsetAsync(maxp, 0, 4);
    cudaMemsetAsync(cntp, 0, NTASK * sizeof(int));
    cudaMemsetAsync(nip, 0, 4);

    // (1) prep (+x init) and proj identity check
    prep_kernel<<<10560, 256>>>(features, task, W1, projW);
    projchk_kernel<<<1024, 256>>>(projW);

    // (2) G exact fp32
    gram_kernel<<<dim3(8, 8), 256>>>(W1);

    // (3) h: split-K=2, 3-term tf32, BK=16
    gemm_tf32<16, true, 0><<<dim3(HDIM / BN, BATCH / BM, 2), 256, smem_h>>>(
        fhi, flo, FDIM, w1hi, w1lo, FDIM, hpart, HDIM, FDIM / 2, BATCH * HDIM, nullptr);
    hreduce_kernel<<<BATCH * HDIM / 1024, 256>>>(b1);

    // (4-6) coeffs, unc, gate+compact
    coeffs_kernel<<<BATCH / 32, 256>>>(W2, b2);
    unc_kernel<<<BATCH / 8, 256>>>(W2);
    gate_kernel<<<(BATCH * NTASK + 255) / 256, 256>>>(bthr, beta);

    // (7..) chain: manual-mma gathered GEMM, in-place fp32 x, rounded ping-pong
    dim3 gC(FDIM / 64, BATCH / 128);     // 16 x 64
    const float* around = fhi;
    float* nextr = xar;
    for (int j = 0; j < NTASK; j++) {
        copy_round_inactive<<<BATCH, 256>>>(around, nextr, j);
        gemm_chain<<<gC, 256, smem_c>>>(
            around, thi + (size_t)j * FDIM * FDIM, xa, gated, j, nextr,
            idxp + j * BATCH, cntp + j);
        around = nextr;
        nextr = (around == xar) ? xbr : xar;
    }

    // final split (no-op when proj == I)
    splitx_kernel<<<BATCH * FDIM / 4096, 256>>>(xa);

    // proj: identity -> copy, else 3-term GEMM
    gemm_tf32<32, true, 5><<<dim3(FDIM / BN, BATCH / BM), 256, smem_p>>>(
        fhi, flo, FDIM, phi, plo, FDIM, out, FDIM, FDIM, 0, xa);
}

// round 15
// speedup vs baseline: 2.2156x; 1.0906x over previous
#include <cuda_runtime.h>
#include <mma.h>
#include <cstdint>
#include <cstddef>

using namespace nvcuda;

#define BATCH 8192
#define FDIM  1024
#define HDIM  256
#define NTASK 8

// ---------------- scratch (static device globals; no allocation) ----------------
__device__ float g_fhi[BATCH * FDIM], g_flo[BATCH * FDIM];   // features tf32 split; reused for final-x split
__device__ float g_W1hi[HDIM * FDIM], g_W1lo[HDIM * FDIM];
__device__ float g_Thi[NTASK * FDIM * FDIM];                 // task mats transposed to [N,K], tf32
__device__ float g_Phi[FDIM * FDIM], g_Plo[FDIM * FDIM];     // projW split ([N,K] layout already)
__device__ float g_xa[BATCH * FDIM];                         // chain x, updated IN PLACE
__device__ float g_xar[BATCH * FDIM], g_xbr[BATCH * FDIM];   // tf32-rounded x ping-pong (A operand)
__device__ float g_hpart[2 * BATCH * HDIM];                  // h split-K partials
__device__ float    g_h[BATCH * HDIM];
__device__ float    g_G[HDIM * HDIM];
__device__ float    g_coeffs[BATCH * NTASK];
__device__ float    g_unc2[BATCH * NTASK];
__device__ unsigned g_max2bits;
__device__ float    g_gated[BATCH * NTASK];
__device__ int      g_cnt[NTASK];
__device__ int      g_idx[NTASK * BATCH];
__device__ unsigned g_notident;

// ---------------- cp.async helpers ----------------
__device__ __forceinline__ void cp16(float* s, const float* g) {
    unsigned sa = (unsigned)__cvta_generic_to_shared(s);
    asm volatile("cp.async.cg.shared.global [%0], [%1], 16;" :: "r"(sa), "l"(g));
}
__device__ __forceinline__ void cp_commit() { asm volatile("cp.async.commit_group;"); }
template <int N> __device__ __forceinline__ void cp_wait() {
    asm volatile("cp.async.wait_group %0;" :: "n"(N));
}

// ---------------- manual mma helpers ----------------
__device__ __forceinline__ void ldsm4(uint32_t& r0, uint32_t& r1, uint32_t& r2, uint32_t& r3,
                                      uint32_t addr) {
    asm volatile("ldmatrix.sync.aligned.m8n8.x4.shared.b16 {%0,%1,%2,%3}, [%4];"
        : "=r"(r0), "=r"(r1), "=r"(r2), "=r"(r3) : "r"(addr));
}
__device__ __forceinline__ void mma_tf32(float* d, const uint32_t* a, const uint32_t* b) {
    asm volatile("mma.sync.aligned.m16n8k8.row.col.f32.tf32.tf32.f32 "
        "{%0,%1,%2,%3}, {%4,%5,%6,%7}, {%8,%9}, {%0,%1,%2,%3};"
        : "+f"(d[0]), "+f"(d[1]), "+f"(d[2]), "+f"(d[3])
        : "r"(a[0]), "r"(a[1]), "r"(a[2]), "r"(a[3]), "r"(b[0]), "r"(b[1]));
}

// ================= chain GEMM: 128x64x32, 8 warps @ 32x32, manual mma + ldmatrix (proven R13) ===
constexpr int CLD = 36;                          // 32 + 4 pad (floats)
constexpr int CASZ = 128 * CLD;
constexpr int CBSZ = 64 * CLD;
constexpr int CSTAGE = CASZ + CBSZ;

__global__ void __launch_bounds__(256, 2) gemm_chain(
    const float* __restrict__ A,                // rounded x  [BATCH, FDIM]
    const float* __restrict__ Bm,               // T^T tf32   [FDIM, FDIM] ([N,K])
    float* C,                                   // fp32 x, in-place
    const float* __restrict__ gate, int gcol,
    float* __restrict__ Cr,                     // next rounded buffer
    const int* __restrict__ idx, const int* __restrict__ cnt)
{
    extern __shared__ float smem[];
    __shared__ int sidx[128];

    const int tid = threadIdx.x;
    const int lane = tid & 31;
    const int warp = tid >> 5;
    const int m0 = blockIdx.y * 128;
    const int n0 = blockIdx.x * 64;
    const int wm0 = (warp >> 1) * 32;            // 0..3 -> 32-row slice
    const int wn0 = (warp & 1) * 32;             // 0..1 -> 32-col slice

    const int n_act = *cnt;
    if (m0 >= n_act) return;
    if (tid < 128) {
        int m = m0 + tid;
        sidx[tid] = (m < n_act) ? idx[m] : idx[m0];
    }
    __syncthreads();

    float acc[2][4][4];
#pragma unroll
    for (int mi = 0; mi < 2; mi++)
#pragma unroll
        for (int nj = 0; nj < 4; nj++)
#pragma unroll
            for (int c = 0; c < 4; c++) acc[mi][nj][c] = 0.0f;

    auto load_stage = [&](int s, int k0) {
        float* as = smem + s * CSTAGE;
        float* bs = as + CASZ;
#pragma unroll
        for (int i = 0; i < 4; i++) {
            int e = i * 256 + tid;
            int r = e >> 3, c = (e & 7) << 2;
            cp16(&as[r * CLD + c], &A[(size_t)sidx[r] * FDIM + k0 + c]);
        }
#pragma unroll
        for (int i = 0; i < 2; i++) {
            int e = i * 256 + tid;
            int r = e >> 3, c = (e & 7) << 2;
            cp16(&bs[r * CLD + c], &Bm[(size_t)(n0 + r) * FDIM + k0 + c]);
        }
    };

    load_stage(0, 0);
    cp_commit();

    const uint32_t smb = (uint32_t)__cvta_generic_to_shared(smem);
    const uint32_t aoff = ((wm0 + (lane & 15)) * CLD + ((lane >> 4) << 2)) * 4;
    const uint32_t boff = (CASZ + ((wn0 + (lane & 7) + ((lane >> 4) << 3)) * CLD
                          + (((lane >> 3) & 1) << 2))) * 4;

    constexpr int ITERS = FDIM / 32;
    for (int it = 0; it < ITERS; it++) {
        if (it + 1 < ITERS) load_stage((it + 1) & 1, (it + 1) * 32);
        cp_commit();              // empty group on last iter keeps counts aligned
        cp_wait<1>();
        __syncthreads();

        const uint32_t sa = smb + (uint32_t)((it & 1) * CSTAGE) * 4;
        const uint32_t aaddr  = sa + aoff;
        const uint32_t aaddr2 = aaddr + 16 * CLD * 4;
        const uint32_t baddr  = sa + boff;
        const uint32_t baddr2 = baddr + 16 * CLD * 4;

#pragma unroll
        for (int kk = 0; kk < 4; kk++) {
            uint32_t a[2][4], b[4][2];
            ldsm4(a[0][0], a[0][1], a[0][2], a[0][3], aaddr  + kk * 32);
            ldsm4(a[1][0], a[1][1], a[1][2], a[1][3], aaddr2 + kk * 32);
            ldsm4(b[0][0], b[0][1], b[1][0], b[1][1], baddr  + kk * 32);
            ldsm4(b[2][0], b[2][1], b[3][0], b[3][1], baddr2 + kk * 32);
#pragma unroll
            for (int mi = 0; mi < 2; mi++)
#pragma unroll
                for (int nj = 0; nj < 4; nj++)
                    mma_tf32(acc[mi][nj], a[mi], b[nj]);
        }
        __syncthreads();
    }

    // epilogue: fragment store to smem, gathered gated in-place update
    constexpr int SLD = 68;
    float* St = smem;
#pragma unroll
    for (int mi = 0; mi < 2; mi++)
#pragma unroll
        for (int nj = 0; nj < 4; nj++) {
            int r = wm0 + mi * 16 + (lane >> 2);
            int cc = wn0 + nj * 8 + (lane & 3) * 2;
            St[r * SLD + cc]           = acc[mi][nj][0];
            St[r * SLD + cc + 1]       = acc[mi][nj][1];
            St[(r + 8) * SLD + cc]     = acc[mi][nj][2];
            St[(r + 8) * SLD + cc + 1] = acc[mi][nj][3];
        }
    __syncthreads();
#pragma unroll
    for (int it = 0; it < 8; it++) {
        int e = it * 256 + tid;
        int r = e >> 4, c = (e & 15) << 2;
        if (m0 + r >= n_act) continue;
        int grow = sidx[r];
        size_t ix = (size_t)grow * FDIM + n0 + c;
        float g = gate[grow * NTASK + gcol];
        float4 v = *(const float4*)&St[r * SLD + c];
        float4 rs = *(const float4*)&C[ix];
        v.x = rs.x + g * v.x; v.y = rs.y + g * v.y;
        v.z = rs.z + g * v.z; v.w = rs.w + g * v.w;
        *(float4*)&C[ix] = v;
        float4 t;
        t.x = wmma::__float_to_tf32(v.x); t.y = wmma::__float_to_tf32(v.y);
        t.z = wmma::__float_to_tf32(v.z); t.w = wmma::__float_to_tf32(v.w);
        *(float4*)&Cr[ix] = t;
    }
}

// ================= h GEMM: manual mma, 3-term tf32, 128x64x16, split-K via z ==================
constexpr int HLD = 20;                          // 16 + 4 pad
constexpr int HASZ = 128 * HLD;                  // 2560
constexpr int HBSZ = 64 * HLD;                   // 1280
constexpr int HSTAGE = 2 * (HASZ + HBSZ);        // 7680 floats (Ahi,Alo,Bhi,Blo)

__global__ void __launch_bounds__(256, 2) gemm_h(
    const float* __restrict__ Ahi, const float* __restrict__ Alo,
    const float* __restrict__ Bhi, const float* __restrict__ Blo,
    float* __restrict__ C)                       // hpart, z-sliced
{
    extern __shared__ float smem[];

    const int tid = threadIdx.x;
    const int lane = tid & 31;
    const int warp = tid >> 5;
    const int m0 = blockIdx.y * 128;
    const int n0 = blockIdx.x * 64;
    const int wm0 = (warp >> 1) * 32;
    const int wn0 = (warp & 1) * 32;
    const int koff = blockIdx.z * (FDIM / 2);

    float acc[2][4][4];
#pragma unroll
    for (int mi = 0; mi < 2; mi++)
#pragma unroll
        for (int nj = 0; nj < 4; nj++)
#pragma unroll
            for (int c = 0; c < 4; c++) acc[mi][nj][c] = 0.0f;

    auto load_stage = [&](int s, int k0) {
        float* ah = smem + s * HSTAGE;
        float* al = ah + HASZ;
        float* bh = al + HASZ;
        float* bl = bh + HBSZ;
#pragma unroll
        for (int i = 0; i < 2; i++) {
            int e = i * 256 + tid;
            int r = e >> 2, c = (e & 3) << 2;
            size_t gix = (size_t)(m0 + r) * FDIM + koff + k0 + c;
            cp16(&ah[r * HLD + c], &Ahi[gix]);
            cp16(&al[r * HLD + c], &Alo[gix]);
        }
        {
            int r = tid >> 2, c = (tid & 3) << 2;
            size_t gix = (size_t)(n0 + r) * FDIM + koff + k0 + c;
            cp16(&bh[r * HLD + c], &Bhi[gix]);
            cp16(&bl[r * HLD + c], &Blo[gix]);
        }
    };

    load_stage(0, 0);
    cp_commit();

    const uint32_t smb = (uint32_t)__cvta_generic_to_shared(smem);
    const uint32_t aoff = ((wm0 + (lane & 15)) * HLD + ((lane >> 4) << 2)) * 4;
    const uint32_t boff = ((wn0 + (lane & 7) + ((lane >> 4) << 3)) * HLD
                          + (((lane >> 3) & 1) << 2)) * 4;

    constexpr int ITERS = (FDIM / 2) / 16;       // 32
    for (int it = 0; it < ITERS; it++) {
        if (it + 1 < ITERS) load_stage((it + 1) & 1, (it + 1) * 16);
        cp_commit();
        cp_wait<1>();
        __syncthreads();

        const uint32_t sa = smb + (uint32_t)((it & 1) * HSTAGE) * 4;
        const uint32_t ah1 = sa + aoff;
        const uint32_t ah2 = ah1 + 16 * HLD * 4;
        const uint32_t al1 = ah1 + HASZ * 4;
        const uint32_t al2 = al1 + 16 * HLD * 4;
        const uint32_t bh1 = sa + 2 * HASZ * 4 + boff;
        const uint32_t bh2 = bh1 + 16 * HLD * 4;
        const uint32_t bl1 = bh1 + HBSZ * 4;
        const uint32_t bl2 = bl1 + 16 * HLD * 4;

#pragma unroll
        for (int kk = 0; kk < 2; kk++) {
            uint32_t ah[2][4], al[2][4], bh[4][2], bl[4][2];
            ldsm4(ah[0][0], ah[0][1], ah[0][2], ah[0][3], ah1 + kk * 32);
            ldsm4(ah[1][0], ah[1][1], ah[1][2], ah[1][3], ah2 + kk * 32);
            ldsm4(al[0][0], al[0][1], al[0][2], al[0][3], al1 + kk * 32);
            ldsm4(al[1][0], al[1][1], al[1][2], al[1][3], al2 + kk * 32);
            ldsm4(bh[0][0], bh[0][1], bh[1][0], bh[1][1], bh1 + kk * 32);
            ldsm4(bh[2][0], bh[2][1], bh[3][0], bh[3][1], bh2 + kk * 32);
            ldsm4(bl[0][0], bl[0][1], bl[1][0], bl[1][1], bl1 + kk * 32);
            ldsm4(bl[2][0], bl[2][1], bl[3][0], bl[3][1], bl2 + kk * 32);
#pragma unroll
            for (int mi = 0; mi < 2; mi++)
#pragma unroll
                for (int nj = 0; nj < 4; nj++) {
                    mma_tf32(acc[mi][nj], ah[mi], bl[nj]);
                    mma_tf32(acc[mi][nj], al[mi], bh[nj]);
                    mma_tf32(acc[mi][nj], ah[mi], bh[nj]);
                }
        }
        __syncthreads();
    }

    // epilogue: fragment store to smem, plain store with z-slice offset
    constexpr int SLD = 68;
    float* St = smem;
#pragma unroll
    for (int mi = 0; mi < 2; mi++)
#pragma unroll
        for (int nj = 0; nj < 4; nj++) {
            int r = wm0 + mi * 16 + (lane >> 2);
            int cc = wn0 + nj * 8 + (lane & 3) * 2;
            St[r * SLD + cc]           = acc[mi][nj][0];
            St[r * SLD + cc + 1]       = acc[mi][nj][1];
            St[(r + 8) * SLD + cc]     = acc[mi][nj][2];
            St[(r + 8) * SLD + cc + 1] = acc[mi][nj][3];
        }
    __syncthreads();
#pragma unroll
    for (int it = 0; it < 8; it++) {
        int e = it * 256 + tid;
        int r = e >> 4, c = (e & 15) << 2;
        size_t ix = (size_t)blockIdx.z * (BATCH * HDIM) + (size_t)(m0 + r) * HDIM + n0 + c;
        *(float4*)&C[ix] = *(const float4*)&St[r * SLD + c];
    }
}

// ================= narrow wmma GEMM (proj != I fallback only) =================
constexpr int BM = 128, BN = 64;

template <int BKT, bool THREE, int EPI>
__global__ void __launch_bounds__(256, 2) gemm_tf32(
    const float* __restrict__ A, const float* __restrict__ Alo, int lda,
    const float* __restrict__ Bm, const float* __restrict__ Blo, int ldb,
    float* C, int ldc, int Kdim, int zstride,
    const float* resid)
{
    constexpr int ALD = BKT + 4;
    constexpr int ASZ = BM * ALD;
    constexpr int BSZ = BN * ALD;
    constexpr int NTA = THREE ? 2 : 1;
    constexpr int STAGE = NTA * (ASZ + BSZ);
    constexpr int AQ = BKT / 4;
    constexpr int AIT = BM * AQ / 256;
    constexpr int BIT = BN * AQ / 256;

    extern __shared__ float smem[];

    const int tid = threadIdx.x;
    const int m0 = blockIdx.y * BM;
    const int n0 = blockIdx.x * BN;
    const int warp = tid >> 5;
    const int wm = warp >> 1;
    const int wn = warp & 1;
    const int koff = blockIdx.z * Kdim;

    if (EPI == 5) {
        if (g_notident == 0u) {    // proj == identity: copy resid tile
#pragma unroll
            for (int it = 0; it < 8; it++) {
                int e = it * 256 + tid;
                int r = e >> 4, c = (e & 15) << 2;
                size_t ix = (size_t)(m0 + r) * ldc + n0 + c;
                *(float4*)&C[ix] = *(const float4*)&resid[ix];
            }
            return;
        }
    }

    wmma::fragment<wmma::accumulator, 16, 16, 8, float> acc[2][2];
#pragma unroll
    for (int i = 0; i < 2; i++)
#pragma unroll
        for (int j = 0; j < 2; j++) wmma::fill_fragment(acc[i][j], 0.0f);

    const int iters = Kdim / BKT;

    auto load_stage = [&](int s, int k0) {
        float* as = smem + s * STAGE;
        float* al = as + ASZ;
        float* bs = as + NTA * ASZ;
        float* bl = bs + BSZ;
#pragma unroll
        for (int i = 0; i < AIT; i++) {
            int e = i * 256 + tid;
            int r = e / AQ, c = (e % AQ) << 2;
            cp16(&as[r * ALD + c], &A[(size_t)(m0 + r) * lda + koff + k0 + c]);
            if (THREE) cp16(&al[r * ALD + c], &Alo[(size_t)(m0 + r) * lda + koff + k0 + c]);
        }
#pragma unroll
        for (int i = 0; i < BIT; i++) {
            int e = i * 256 + tid;
            int r = e / AQ, c = (e % AQ) << 2;
            cp16(&bs[r * ALD + c], &Bm[(size_t)(n0 + r) * ldb + koff + k0 + c]);
            if (THREE) cp16(&bl[r * ALD + c], &Blo[(size_t)(n0 + r) * ldb + koff + k0 + c]);
        }
    };

    load_stage(0, 0);
    cp_commit();

    for (int it = 0; it < iters; it++) {
        if (it + 1 < iters) load_stage((it + 1) & 1, (it + 1) * BKT);
        cp_commit();
        cp_wait<1>();
        __syncthreads();

        const float* as = smem + (it & 1) * STAGE;
        const float* al = as + ASZ;
        const float* bs = as + NTA * ASZ;
        const float* bl = bs + BSZ;

#pragma unroll
        for (int kk = 0; kk < BKT / 8; kk++) {
            wmma::fragment<wmma::matrix_a, 16, 16, 8, wmma::precision::tf32, wmma::row_major> af[2], afl[THREE ? 2 : 1];
            wmma::fragment<wmma::matrix_b, 16, 16, 8, wmma::precision::tf32, wmma::col_major> bf[2], bfl[THREE ? 2 : 1];
#pragma unroll
            for (int i = 0; i < 2; i++) {
                wmma::load_matrix_sync(af[i], &as[(wm * 32 + i * 16) * ALD + kk * 8], ALD);
                if (THREE)
                    wmma::load_matrix_sync(afl[i], &al[(wm * 32 + i * 16) * ALD + kk * 8], ALD);
            }
#pragma unroll
            for (int j = 0; j < 2; j++) {
                wmma::load_matrix_sync(bf[j], &bs[(wn * 32 + j * 16) * ALD + kk * 8], ALD);
                if (THREE)
                    wmma::load_matrix_sync(bfl[j], &bl[(wn * 32 + j * 16) * ALD + kk * 8], ALD);
            }
#pragma unroll
            for (int i = 0; i < 2; i++)
#pragma unroll
                for (int j = 0; j < 2; j++) {
                    if (THREE) {
                        wmma::mma_sync(acc[i][j], af[i], bfl[j], acc[i][j]);
                        wmma::mma_sync(acc[i][j], afl[i], bf[j], acc[i][j]);
                    }
                    wmma::mma_sync(acc[i][j], af[i], bf[j], acc[i][j]);
                }
        }
        __syncthreads();
    }

    constexpr int SLD = BN + 4;
    float* St = smem;
#pragma unroll
    for (int i = 0; i < 2; i++)
#pragma unroll
        for (int j = 0; j < 2; j++)
            wmma::store_matrix_sync(&St[(wm * 32 + i * 16) * SLD + wn * 32 + j * 16],
                                    acc[i][j], SLD, wmma::mem_row_major);
    __syncthreads();
#pragma unroll
    for (int it = 0; it < 8; it++) {
        int e = it * 256 + tid;
        int r = e >> 4, c = (e & 15) << 2;
        float4 v = *(const float4*)&St[r * SLD + c];
        size_t ix = (size_t)blockIdx.z * zstride + (size_t)(m0 + r) * ldc + n0 + c;
        *(float4*)&C[ix] = v;
    }
}

// ---------------- G = W1 @ W1^T in exact fp32 (SIMT, smem-tiled) ----------------
__global__ void __launch_bounds__(256) gram_kernel(const float* __restrict__ W1)
{
    __shared__ float As[32][33], Bs[32][33];
    const int tid = threadIdx.x;
    const int r0 = blockIdx.y * 32, c0 = blockIdx.x * 32;
    const int ty = tid >> 4, tx = tid & 15;
    float a00 = 0.f, a01 = 0.f, a10 = 0.f, a11 = 0.f;

    for (int k0 = 0; k0 < FDIM; k0 += 32) {
#pragma unroll
        for (int i = 0; i < 4; i++) {
            int e = i * 256 + tid;
            int r = e >> 5, c = e & 31;
            As[r][c] = W1[(size_t)(r0 + r) * FDIM + k0 + c];
            Bs[r][c] = W1[(size_t)(c0 + r) * FDIM + k0 + c];
        }
        __syncthreads();
#pragma unroll 8
        for (int k = 0; k < 32; k++) {
            float x0 = As[ty * 2][k],     x1 = As[ty * 2 + 1][k];
            float y0 = Bs[tx * 2][k],     y1 = Bs[tx * 2 + 1][k];
            a00 = fmaf(x0, y0, a00); a01 = fmaf(x0, y1, a01);
            a10 = fmaf(x1, y0, a10); a11 = fmaf(x1, y1, a11);
        }
        __syncthreads();
    }
    int gr = r0 + ty * 2, gc = c0 + tx * 2;
    g_G[gr * HDIM + gc] = a00;       g_G[gr * HDIM + gc + 1] = a01;
    g_G[(gr + 1) * HDIM + gc] = a10; g_G[(gr + 1) * HDIM + gc + 1] = a11;
}

// ---------------- h reduce ----------------
__global__ void __launch_bounds__(256) hreduce_kernel(const float* __restrict__ b1)
{
    int e = blockIdx.x * 256 + threadIdx.x;
    size_t ix = (size_t)e * 4;
    int col = (int)(ix & (HDIM - 1));
    float4 p0 = *(const float4*)&g_hpart[ix];
    float4 p1 = *(const float4*)&g_hpart[(size_t)BATCH * HDIM + ix];
    float4 v;
    v.x = p0.x + p1.x + b1[col];
    v.y = p0.y + p1.y + b1[col + 1];
    v.z = p0.z + p1.z + b1[col + 2];
    v.w = p0.w + p1.w + b1[col + 3];
    *(float4*)&g_h[ix] = v;
}

// ---------------- prep ----------------
__global__ void __launch_bounds__(256) prep_kernel(
    const float* __restrict__ F, const float* __restrict__ T,
    const float* __restrict__ W1, const float* __restrict__ P)
{
    int b = blockIdx.x, tid = threadIdx.x;
    if (b < 8192) {
        __shared__ float s[32][33];
        int j = b >> 10, t = b & 1023;
        int tr = t >> 5, tc = t & 31;
        int x = tid & 31, y = tid >> 5;
        const float* src = T + (size_t)j * FDIM * FDIM;
#pragma unroll
        for (int i = 0; i < 4; i++)
            s[y + i * 8][x] = src[(size_t)(tr * 32 + y + i * 8) * FDIM + tc * 32 + x];
        __syncthreads();
        float* dh = g_Thi + (size_t)j * FDIM * FDIM;
#pragma unroll
        for (int i = 0; i < 4; i++) {
            int n = tc * 32 + y + i * 8, k = tr * 32 + x;
            dh[(size_t)n * FDIM + k] = wmma::__float_to_tf32(s[x][y + i * 8]);
        }
    } else if (b < 10240) {
        size_t base = (size_t)(b - 8192) * 4096 + tid * 16;
#pragma unroll
        for (int q = 0; q < 4; q++) {
            float4 v = *(const float4*)&F[base + q * 4];
            *(float4*)&g_xa[base + q * 4] = v;
            float vv[4] = {v.x, v.y, v.z, v.w};
#pragma unroll
            for (int e = 0; e < 4; e++) {
                size_t ix = base + q * 4 + e;
                float hi = wmma::__float_to_tf32(vv[e]);
                g_fhi[ix] = hi;
                g_flo[ix] = wmma::__float_to_tf32(vv[e] - hi);
            }
        }
    } else if (b < 10304) {
        size_t base = (size_t)(b - 10240) * 4096 + tid * 16;
#pragma unroll
        for (int q = 0; q < 4; q++) {
            float4 v = *(const float4*)&W1[base + q * 4];
            float vv[4] = {v.x, v.y, v.z, v.w};
#pragma unroll
            for (int e = 0; e < 4; e++) {
                size_t ix = base + q * 4 + e;
                float hi = wmma::__float_to_tf32(vv[e]);
                g_W1hi[ix] = hi;
                g_W1lo[ix] = wmma::__float_to_tf32(vv[e] - hi);
            }
        }
    } else {
        size_t base = (size_t)(b - 10304) * 4096 + tid * 16;
#pragma unroll
        for (int q = 0; q < 4; q++) {
            float4 v = *(const float4*)&P[base + q * 4];
            float vv[4] = {v.x, v.y, v.z, v.w};
#pragma unroll
            for (int e = 0; e < 4; e++) {
                size_t ix = base + q * 4 + e;
                float hi = wmma::__float_to_tf32(vv[e]);
                g_Phi[ix] = hi;
                g_Plo[ix] = wmma::__float_to_tf32(vv[e] - hi);
            }
        }
    }
}

// ---------------- proj identity check ----------------
__global__ void projchk_kernel(const float* __restrict__ P)
{
    int e = blockIdx.x * 256 + threadIdx.x;
    int idx4 = e * 4;
    int row = idx4 >> 10;
    float4 v = *(const float4*)&P[idx4];
    float vv[4] = {v.x, v.y, v.z, v.w};
    bool bad = false;
#pragma unroll
    for (int q = 0; q < 4; q++) {
        int col = (idx4 + q) & 1023;
        float exp = (col == row) ? 1.0f : 0.0f;
        if (vv[q] != exp) bad = true;
    }
    if (__syncthreads_or(bad) && threadIdx.x == 0) atomicOr(&g_notident, 1u);
}

// ---------------- split final x (only if proj != I) ----------------
__global__ void __launch_bounds__(256) splitx_kernel(const float* __restrict__ X)
{
    if (g_notident == 0u) return;
    size_t base = (size_t)blockIdx.x * 4096 + threadIdx.x * 16;
#pragma unroll
    for (int q = 0; q < 4; q++) {
        float4 v = *(const float4*)&X[base + q * 4];
        float vv[4] = {v.x, v.y, v.z, v.w};
#pragma unroll
        for (int e = 0; e < 4; e++) {
            size_t ix = base + q * 4 + e;
            float hi = wmma::__float_to_tf32(vv[e]);
            g_fhi[ix] = hi;
            g_flo[ix] = wmma::__float_to_tf32(vv[e] - hi);
        }
    }
}

// ---------------- coeffs ----------------
__global__ void coeffs_kernel(const float* __restrict__ W2, const float* __restrict__ b2)
{
    int tid = threadIdx.x;
    int row = blockIdx.x * 32 + (tid >> 3);
    int k = tid & 7;
    const float* hr = g_h + (size_t)row * HDIM;
    const float* w = W2 + k * HDIM;
    float s = b2[k];
#pragma unroll 8
    for (int h = 0; h < HDIM; h++) s += fmaxf(hr[h], 0.0f) * w[h];
    g_coeffs[row * NTASK + k] = s;
}

// ---------------- unc ----------------
__global__ void __launch_bounds__(256) unc_kernel(const float* __restrict__ W2)
{
    __shared__ float W2s[NTASK * HDIM];
    __shared__ float Gs[HDIM * 32];
    int tid = threadIdx.x, lane = tid & 31, warp = tid >> 5;
    for (int i = tid; i < NTASK * HDIM; i += 256) W2s[i] = W2[i];

    int row = blockIdx.x * 8 + warp;
    const float* hr = g_h + (size_t)row * HDIM;
    unsigned mb[8];
#pragma unroll
    for (int j = 0; j < 8; j++)
        mb[j] = __ballot_sync(0xffffffffu, hr[j * 32 + lane] > 0.0f);

    float u2[8];
#pragma unroll
    for (int k = 0; k < 8; k++) u2[k] = 0.0f;

    for (int c = 0; c < 8; c++) {
        __syncthreads();
        for (int i = tid; i < HDIM * 32; i += 256) {
            int h = i >> 5, l = i & 31;
            Gs[i] = g_G[h * HDIM + c * 32 + l];
        }
        __syncthreads();
        float t[8];
#pragma unroll
        for (int k = 0; k < 8; k++) t[k] = 0.0f;
        for (int h = 0; h < HDIM; h++) {
            if ((mb[h >> 5] >> (h & 31)) & 1u) {
                float gv = Gs[h * 32 + lane];
#pragma unroll
                for (int k = 0; k < 8; k++) t[k] += W2s[k * HDIM + h] * gv;
            }
        }
        int hp = c * 32 + lane;
        if ((mb[hp >> 5] >> (hp & 31)) & 1u) {
#pragma unroll
            for (int k = 0; k < 8; k++) u2[k] += W2s[k * HDIM + hp] * t[k];
        }
    }
#pragma unroll
    for (int k = 0; k < 8; k++) {
        float v = u2[k];
        for (int off = 16; off; off >>= 1) v += __shfl_down_sync(0xffffffffu, v, off);
        if (lane == 0) {
            v = fmaxf(v, 0.0f);
            g_unc2[row * NTASK + k] = v;
            atomicMax(&g_max2bits, __float_as_uint(v));
        }
    }
}

// ---------------- gating + compaction ----------------
__global__ void gate_kernel(const float* __restrict__ bthr, const float* __restrict__ beta)
{
    int i = blockIdx.x * blockDim.x + threadIdx.x;
    if (i >= BATCH * NTASK) return;
    int row = i >> 3, k = i & 7;
    float max2 = __uint_as_float(g_max2bits);
    float u = (max2 > 0.0f) ? sqrtf(g_unc2[i] / max2) : sqrtf(g_unc2[i]);
    float base = log1pf(expf(bthr[0]));
    float thr = base * (1.0f + fmaxf(beta[0], 0.0f) * u);
    float cf = g_coeffs[i];
    float gf = (fabsf(cf) < thr) ? 0.0f : cf;
    g_gated[i] = gf;
    if (gf != 0.0f) {
        int p = atomicAdd(&g_cnt[k], 1);
        g_idx[k * BATCH + p] = row;
    }
}

// ---------------- copy rounded buffer for zero-gate rows ----------------
__global__ void __launch_bounds__(256) copy_round_inactive(
    const float* __restrict__ rin, float* __restrict__ rout, int j)
{
    int row = blockIdx.x;
    if (g_gated[row * NTASK + j] != 0.0f) return;
    size_t b4 = (size_t)row * (FDIM / 4) + threadIdx.x;
    ((float4*)rout)[b4] = ((const float4*)rin)[b4];
}

// ---------------- launch ----------------
extern "C" void kernel_launch(void* const* d_in, const int* in_sizes, int n_in,
                              void* d_out, int out_size)
{
    const float* features = (const float*)d_in[0];
    const float* W1   = (const float*)d_in[1];
    const float* b1   = (const float*)d_in[2];
    const float* W2   = (const float*)d_in[3];
    const float* b2   = (const float*)d_in[4];
    const float* task = (const float*)d_in[5];
    const float* projW = (const float*)d_in[6];
    const float* bthr = (const float*)d_in[7];
    const float* beta = (const float*)d_in[8];
    float* out = (float*)d_out;

    float *fhi, *flo, *w1hi, *w1lo, *thi, *phi, *plo;
    float *xa, *xar, *xbr, *hpart, *gated;
    int *idxp, *cntp;
    void *maxp, *nip;
    cudaGetSymbolAddress((void**)&fhi, g_fhi);   cudaGetSymbolAddress((void**)&flo, g_flo);
    cudaGetSymbolAddress((void**)&w1hi, g_W1hi); cudaGetSymbolAddress((void**)&w1lo, g_W1lo);
    cudaGetSymbolAddress((void**)&thi, g_Thi);
    cudaGetSymbolAddress((void**)&phi, g_Phi);   cudaGetSymbolAddress((void**)&plo, g_Plo);
    cudaGetSymbolAddress((void**)&xa, g_xa);
    cudaGetSymbolAddress((void**)&xar, g_xar);   cudaGetSymbolAddress((void**)&xbr, g_xbr);
    cudaGetSymbolAddress((void**)&hpart, g_hpart);
    cudaGetSymbolAddress((void**)&gated, g_gated);
    cudaGetSymbolAddress((void**)&idxp, g_idx);  cudaGetSymbolAddress((void**)&cntp, g_cnt);
    cudaGetSymbolAddress(&maxp, g_max2bits);     cudaGetSymbolAddress(&nip, g_notident);

    const int smem_h  = 2 * HSTAGE * 4;                       // 61440
    const int smem_p  = 2 * 2 * (BM * 36 + BN * 36) * 4;      // 110592
    const int smem_c  = 2 * CSTAGE * 4;                       // 55296
    cudaFuncSetAttribute(gemm_h, cudaFuncAttributeMaxDynamicSharedMemorySize, smem_h);
    cudaFuncSetAttribute(gemm_tf32<32, true, 5>, cudaFuncAttributeMaxDynamicSharedMemorySize, smem_p);
    cudaFuncSetAttribute(gemm_chain, cudaFuncAttributeMaxDynamicSharedMemorySize, smem_c);

    cudaMemsetAsync(maxp, 0, 4);
    cudaMemsetAsync(cntp, 0, NTASK * sizeof(int));
    cudaMemsetAsync(nip, 0, 4);

    // (1) prep (+x init) and proj identity check
    prep_kernel<<<10560, 256>>>(features, task, W1, projW);
    projchk_kernel<<<1024, 256>>>(projW);

    // (2) G exact fp32
    gram_kernel<<<dim3(8, 8), 256>>>(W1);

    // (3) h: split-K=2, 3-term tf32 manual mma, then fixed-order reduce
    gemm_h<<<dim3(HDIM / 64, BATCH / 128, 2), 256, smem_h>>>(
        fhi, flo, w1hi, w1lo, hpart);
    hreduce_kernel<<<BATCH * HDIM / 1024, 256>>>(b1);

    // (4-6) coeffs, unc, gate+compact
    coeffs_kernel<<<BATCH / 32, 256>>>(W2, b2);
    unc_kernel<<<BATCH / 8, 256>>>(W2);
    gate_kernel<<<(BATCH * NTASK + 255) / 256, 256>>>(bthr, beta);

    // (7..) chain: manual-mma gathered GEMM, in-place fp32 x, rounded ping-pong
    dim3 gC(FDIM / 64, BATCH / 128);     // 16 x 64
    const float* around = fhi;
    float* nextr = xar;
    for (int j = 0; j < NTASK; j++) {
        copy_round_inactive<<<BATCH, 256>>>(around, nextr, j);
        gemm_chain<<<gC, 256, smem_c>>>(
            around, thi + (size_t)j * FDIM * FDIM, xa, gated, j, nextr,
            idxp + j * BATCH, cntp + j);
        around = nextr;
        nextr = (around == xar) ? xbr : xar;
    }

    // final split (no-op when proj == I)
    splitx_kernel<<<BATCH * FDIM / 4096, 256>>>(xa);

    // proj: identity -> copy, else 3-term GEMM
    gemm_tf32<32, true, 5><<<dim3(FDIM / BN, BATCH / BM), 256, smem_p>>>(
        fhi, flo, FDIM, phi, plo, FDIM, out, FDIM, FDIM, 0, xa);
}

// round 17
// speedup vs baseline: 2.2476x; 1.0145x over previous
#include <cuda_runtime.h>
#include <mma.h>
#include <cstdint>
#include <cstddef>

using namespace nvcuda;

#define BATCH 8192
#define FDIM  1024
#define HDIM  256
#define NTASK 8

// ---------------- scratch (static device globals; no allocation) ----------------
__device__ float g_fhi[BATCH * FDIM], g_flo[BATCH * FDIM];   // features tf32 split; reused for final-x split
__device__ float g_W1hi[HDIM * FDIM], g_W1lo[HDIM * FDIM];
__device__ float g_Thi[NTASK * FDIM * FDIM];                 // task mats transposed to [N,K], tf32
__device__ float g_Phi[FDIM * FDIM], g_Plo[FDIM * FDIM];     // projW split ([N,K] layout already)
__device__ float g_xa[BATCH * FDIM];                         // chain x, updated IN PLACE
__device__ float g_xar[BATCH * FDIM], g_xbr[BATCH * FDIM];   // tf32-rounded x ping-pong (A operand)
__device__ float g_hpart[2 * BATCH * HDIM];                  // h split-K partials
__device__ float    g_h[BATCH * HDIM];
__device__ float    g_G[HDIM * HDIM];
__device__ float    g_coeffs[BATCH * NTASK];
__device__ float    g_unc2[BATCH * NTASK];
__device__ unsigned g_max2bits;
__device__ float    g_gated[BATCH * NTASK];
__device__ int      g_cnt[NTASK];
__device__ int      g_idx[NTASK * BATCH];
__device__ unsigned g_notident;

// ---------------- cp.async helpers ----------------
__device__ __forceinline__ void cp16(float* s, const float* g) {
    unsigned sa = (unsigned)__cvta_generic_to_shared(s);
    asm volatile("cp.async.cg.shared.global [%0], [%1], 16;" :: "r"(sa), "l"(g));
}
__device__ __forceinline__ void cp_commit() { asm volatile("cp.async.commit_group;"); }
template <int N> __device__ __forceinline__ void cp_wait() {
    asm volatile("cp.async.wait_group %0;" :: "n"(N));
}

// ---------------- manual mma helpers ----------------
__device__ __forceinline__ void ldsm4(uint32_t& r0, uint32_t& r1, uint32_t& r2, uint32_t& r3,
                                      uint32_t addr) {
    asm volatile("ldmatrix.sync.aligned.m8n8.x4.shared.b16 {%0,%1,%2,%3}, [%4];"
        : "=r"(r0), "=r"(r1), "=r"(r2), "=r"(r3) : "r"(addr));
}
__device__ __forceinline__ void mma_tf32(float* d, const uint32_t* a, const uint32_t* b) {
    asm volatile("mma.sync.aligned.m16n8k8.row.col.f32.tf32.tf32.f32 "
        "{%0,%1,%2,%3}, {%4,%5,%6,%7}, {%8,%9}, {%0,%1,%2,%3};"
        : "+f"(d[0]), "+f"(d[1]), "+f"(d[2]), "+f"(d[3])
        : "r"(a[0]), "r"(a[1]), "r"(a[2]), "r"(a[3]), "r"(b[0]), "r"(b[1]));
}

// ================= chain GEMM: 128x64x32, 8 warps @ 32x32, manual mma, 3-stage pipeline ========
constexpr int CLD = 36;                          // 32 + 4 pad (floats)
constexpr int CASZ = 128 * CLD;
constexpr int CBSZ = 64 * CLD;
constexpr int CSTAGE = CASZ + CBSZ;              // 6912 floats

__global__ void __launch_bounds__(256, 2) gemm_chain(
    const float* __restrict__ A,                // rounded x  [BATCH, FDIM]
    const float* __restrict__ Bm,               // T^T tf32   [FDIM, FDIM] ([N,K])
    float* C,                                   // fp32 x, in-place
    const float* __restrict__ gate, int gcol,
    float* __restrict__ Cr,                     // next rounded buffer
    const int* __restrict__ idx, const int* __restrict__ cnt)
{
    extern __shared__ float smem[];
    __shared__ int sidx[128];

    const int tid = threadIdx.x;
    const int lane = tid & 31;
    const int warp = tid >> 5;
    const int m0 = blockIdx.y * 128;
    const int n0 = blockIdx.x * 64;
    const int wm0 = (warp >> 1) * 32;            // 0..3 -> 32-row slice
    const int wn0 = (warp & 1) * 32;             // 0..1 -> 32-col slice

    const int n_act = *cnt;
    if (m0 >= n_act) return;
    if (tid < 128) {
        int m = m0 + tid;
        sidx[tid] = (m < n_act) ? idx[m] : idx[m0];
    }
    __syncthreads();

    float acc[2][4][4];
#pragma unroll
    for (int mi = 0; mi < 2; mi++)
#pragma unroll
        for (int nj = 0; nj < 4; nj++)
#pragma unroll
            for (int c = 0; c < 4; c++) acc[mi][nj][c] = 0.0f;

    auto load_stage = [&](int s, int k0) {
        float* as = smem + s * CSTAGE;
        float* bs = as + CASZ;
#pragma unroll
        for (int i = 0; i < 4; i++) {
            int e = i * 256 + tid;
            int r = e >> 3, c = (e & 7) << 2;
            cp16(&as[r * CLD + c], &A[(size_t)sidx[r] * FDIM + k0 + c]);
        }
#pragma unroll
        for (int i = 0; i < 2; i++) {
            int e = i * 256 + tid;
            int r = e >> 3, c = (e & 7) << 2;
            cp16(&bs[r * CLD + c], &Bm[(size_t)(n0 + r) * FDIM + k0 + c]);
        }
    };

    load_stage(0, 0);  cp_commit();
    load_stage(1, 32); cp_commit();

    const uint32_t smb = (uint32_t)__cvta_generic_to_shared(smem);
    const uint32_t aoff = ((wm0 + (lane & 15)) * CLD + ((lane >> 4) << 2)) * 4;
    const uint32_t boff = (CASZ + ((wn0 + (lane & 7) + ((lane >> 4) << 3)) * CLD
                          + (((lane >> 3) & 1) << 2))) * 4;

    constexpr int ITERS = FDIM / 32;             // 32
    int cs = 0, ls = 2;                          // compute stage, load stage
    for (int it = 0; it < ITERS; it++) {
        cp_wait<1>();
        __syncthreads();                         // ONE barrier per iteration

        if (it + 2 < ITERS) load_stage(ls, (it + 2) * 32);
        cp_commit();                             // keep group counts aligned

        const uint32_t sa = smb + (uint32_t)(cs * CSTAGE) * 4;
        const uint32_t aaddr  = sa + aoff;
        const uint32_t aaddr2 = aaddr + 16 * CLD * 4;
        const uint32_t baddr  = sa + boff;
        const uint32_t baddr2 = baddr + 16 * CLD * 4;

#pragma unroll
        for (int kk = 0; kk < 4; kk++) {
            uint32_t a[2][4], b[4][2];
            ldsm4(a[0][0], a[0][1], a[0][2], a[0][3], aaddr  + kk * 32);
            ldsm4(a[1][0], a[1][1], a[1][2], a[1][3], aaddr2 + kk * 32);
            ldsm4(b[0][0], b[0][1], b[1][0], b[1][1], baddr  + kk * 32);
            ldsm4(b[2][0], b[2][1], b[3][0], b[3][1], baddr2 + kk * 32);
#pragma unroll
            for (int mi = 0; mi < 2; mi++)
#pragma unroll
                for (int nj = 0; nj < 4; nj++)
                    mma_tf32(acc[mi][nj], a[mi], b[nj]);
        }
        cs = (cs == 2) ? 0 : cs + 1;
        ls = (ls == 2) ? 0 : ls + 1;
    }
    __syncthreads();                             // all compute done before St reuse

    // epilogue: fragment store to smem, gathered gated in-place update
    constexpr int SLD = 68;
    float* St = smem;
#pragma unroll
    for (int mi = 0; mi < 2; mi++)
#pragma unroll
        for (int nj = 0; nj < 4; nj++) {
            int r = wm0 + mi * 16 + (lane >> 2);
            int cc = wn0 + nj * 8 + (lane & 3) * 2;
            St[r * SLD + cc]           = acc[mi][nj][0];
            St[r * SLD + cc + 1]       = acc[mi][nj][1];
            St[(r + 8) * SLD + cc]     = acc[mi][nj][2];
            St[(r + 8) * SLD + cc + 1] = acc[mi][nj][3];
        }
    __syncthreads();
#pragma unroll
    for (int it = 0; it < 8; it++) {
        int e = it * 256 + tid;
        int r = e >> 4, c = (e & 15) << 2;
        if (m0 + r >= n_act) continue;
        int grow = sidx[r];
        size_t ix = (size_t)grow * FDIM + n0 + c;
        float g = gate[grow * NTASK + gcol];
        float4 v = *(const float4*)&St[r * SLD + c];
        float4 rs = *(const float4*)&C[ix];
        v.x = rs.x + g * v.x; v.y = rs.y + g * v.y;
        v.z = rs.z + g * v.z; v.w = rs.w + g * v.w;
        *(float4*)&C[ix] = v;
        float4 t;
        t.x = wmma::__float_to_tf32(v.x); t.y = wmma::__float_to_tf32(v.y);
        t.z = wmma::__float_to_tf32(v.z); t.w = wmma::__float_to_tf32(v.w);
        *(float4*)&Cr[ix] = t;
    }
}

// ================= h GEMM: manual mma, 3-term tf32, 128x64x16, split-K, 3-stage pipeline ======
constexpr int HLD = 20;                          // 16 + 4 pad
constexpr int HASZ = 128 * HLD;                  // 2560
constexpr int HBSZ = 64 * HLD;                   // 1280
constexpr int HSTAGE = 2 * (HASZ + HBSZ);        // 7680 floats (Ahi,Alo,Bhi,Blo)

__global__ void __launch_bounds__(256, 2) gemm_h(
    const float* __restrict__ Ahi, const float* __restrict__ Alo,
    const float* __restrict__ Bhi, const float* __restrict__ Blo,
    float* __restrict__ C)                       // hpart, z-sliced
{
    extern __shared__ float smem[];

    const int tid = threadIdx.x;
    const int lane = tid & 31;
    const int warp = tid >> 5;
    const int m0 = blockIdx.y * 128;
    const int n0 = blockIdx.x * 64;
    const int wm0 = (warp >> 1) * 32;
    const int wn0 = (warp & 1) * 32;
    const int koff = blockIdx.z * (FDIM / 2);

    float acc[2][4][4];
#pragma unroll
    for (int mi = 0; mi < 2; mi++)
#pragma unroll
        for (int nj = 0; nj < 4; nj++)
#pragma unroll
            for (int c = 0; c < 4; c++) acc[mi][nj][c] = 0.0f;

    auto load_stage = [&](int s, int k0) {
        float* ah = smem + s * HSTAGE;
        float* al = ah + HASZ;
        float* bh = al + HASZ;
        float* bl = bh + HBSZ;
#pragma unroll
        for (int i = 0; i < 2; i++) {
            int e = i * 256 + tid;
            int r = e >> 2, c = (e & 3) << 2;
            size_t gix = (size_t)(m0 + r) * FDIM + koff + k0 + c;
            cp16(&ah[r * HLD + c], &Ahi[gix]);
            cp16(&al[r * HLD + c], &Alo[gix]);
        }
        {
            int r = tid >> 2, c = (tid & 3) << 2;
            size_t gix = (size_t)(n0 + r) * FDIM + koff + k0 + c;
            cp16(&bh[r * HLD + c], &Bhi[gix]);
            cp16(&bl[r * HLD + c], &Blo[gix]);
        }
    };

    load_stage(0, 0);  cp_commit();
    load_stage(1, 16); cp_commit();

    const uint32_t smb = (uint32_t)__cvta_generic_to_shared(smem);
    const uint32_t aoff = ((wm0 + (lane & 15)) * HLD + ((lane >> 4) << 2)) * 4;
    const uint32_t boff = ((wn0 + (lane & 7) + ((lane >> 4) << 3)) * HLD
                          + (((lane >> 3) & 1) << 2)) * 4;

    constexpr int ITERS = (FDIM / 2) / 16;       // 32
    int cs = 0, ls = 2;
    for (int it = 0; it < ITERS; it++) {
        cp_wait<1>();
        __syncthreads();

        if (it + 2 < ITERS) load_stage(ls, (it + 2) * 16);
        cp_commit();

        const uint32_t sa = smb + (uint32_t)(cs * HSTAGE) * 4;
        const uint32_t ah1 = sa + aoff;
        const uint32_t ah2 = ah1 + 16 * HLD * 4;
        const uint32_t al1 = ah1 + HASZ * 4;
        const uint32_t al2 = al1 + 16 * HLD * 4;
        const uint32_t bh1 = sa + 2 * HASZ * 4 + boff;
        const uint32_t bh2 = bh1 + 16 * HLD * 4;
        const uint32_t bl1 = bh1 + HBSZ * 4;
        const uint32_t bl2 = bl1 + 16 * HLD * 4;

#pragma unroll
        for (int kk = 0; kk < 2; kk++) {
            uint32_t ah[2][4], al[2][4], bh[4][2], bl[4][2];
            ldsm4(ah[0][0], ah[0][1], ah[0][2], ah[0][3], ah1 + kk * 32);
            ldsm4(ah[1][0], ah[1][1], ah[1][2], ah[1][3], ah2 + kk * 32);
            ldsm4(al[0][0], al[0][1], al[0][2], al[0][3], al1 + kk * 32);
            ldsm4(al[1][0], al[1][1], al[1][2], al[1][3], al2 + kk * 32);
            ldsm4(bh[0][0], bh[0][1], bh[1][0], bh[1][1], bh1 + kk * 32);
            ldsm4(bh[2][0], bh[2][1], bh[3][0], bh[3][1], bh2 + kk * 32);
            ldsm4(bl[0][0], bl[0][1], bl[1][0], bl[1][1], bl1 + kk * 32);
            ldsm4(bl[2][0], bl[2][1], bl[3][0], bl[3][1], bl2 + kk * 32);
#pragma unroll
            for (int mi = 0; mi < 2; mi++)
#pragma unroll
                for (int nj = 0; nj < 4; nj++) {
                    mma_tf32(acc[mi][nj], ah[mi], bl[nj]);
                    mma_tf32(acc[mi][nj], al[mi], bh[nj]);
                    mma_tf32(acc[mi][nj], ah[mi], bh[nj]);
                }
        }
        cs = (cs == 2) ? 0 : cs + 1;
        ls = (ls == 2) ? 0 : ls + 1;
    }
    __syncthreads();

    // epilogue: fragment store to smem, plain store with z-slice offset
    constexpr int SLD = 68;
    float* St = smem;
#pragma unroll
    for (int mi = 0; mi < 2; mi++)
#pragma unroll
        for (int nj = 0; nj < 4; nj++) {
            int r = wm0 + mi * 16 + (lane >> 2);
            int cc = wn0 + nj * 8 + (lane & 3) * 2;
            St[r * SLD + cc]           = acc[mi][nj][0];
            St[r * SLD + cc + 1]       = acc[mi][nj][1];
            St[(r + 8) * SLD + cc]     = acc[mi][nj][2];
            St[(r + 8) * SLD + cc + 1] = acc[mi][nj][3];
        }
    __syncthreads();
#pragma unroll
    for (int it = 0; it < 8; it++) {
        int e = it * 256 + tid;
        int r = e >> 4, c = (e & 15) << 2;
        size_t ix = (size_t)blockIdx.z * (BATCH * HDIM) + (size_t)(m0 + r) * HDIM + n0 + c;
        *(float4*)&C[ix] = *(const float4*)&St[r * SLD + c];
    }
}

// ================= narrow wmma GEMM (proj != I fallback only) =================
constexpr int BM = 128, BN = 64;

template <int BKT, bool THREE, int EPI>
__global__ void __launch_bounds__(256, 2) gemm_tf32(
    const float* __restrict__ A, const float* __restrict__ Alo, int lda,
    const float* __restrict__ Bm, const float* __restrict__ Blo, int ldb,
    float* C, int ldc, int Kdim, int zstride,
    const float* resid)
{
    constexpr int ALD = BKT + 4;
    constexpr int ASZ = BM * ALD;
    constexpr int BSZ = BN * ALD;
    constexpr int NTA = THREE ? 2 : 1;
    constexpr int STAGE = NTA * (ASZ + BSZ);
    constexpr int AQ = BKT / 4;
    constexpr int AIT = BM * AQ / 256;
    constexpr int BIT = BN * AQ / 256;

    extern __shared__ float smem[];

    const int tid = threadIdx.x;
    const int m0 = blockIdx.y * BM;
    const int n0 = blockIdx.x * BN;
    const int warp = tid >> 5;
    const int wm = warp >> 1;
    const int wn = warp & 1;
    const int koff = blockIdx.z * Kdim;

    if (EPI == 5) {
        if (g_notident == 0u) {    // proj == identity: copy resid tile
#pragma unroll
            for (int it = 0; it < 8; it++) {
                int e = it * 256 + tid;
                int r = e >> 4, c = (e & 15) << 2;
                size_t ix = (size_t)(m0 + r) * ldc + n0 + c;
                *(float4*)&C[ix] = *(const float4*)&resid[ix];
            }
            return;
        }
    }

    wmma::fragment<wmma::accumulator, 16, 16, 8, float> acc[2][2];
#pragma unroll
    for (int i = 0; i < 2; i++)
#pragma unroll
        for (int j = 0; j < 2; j++) wmma::fill_fragment(acc[i][j], 0.0f);

    const int iters = Kdim / BKT;

    auto load_stage = [&](int s, int k0) {
        float* as = smem + s * STAGE;
        float* al = as + ASZ;
        float* bs = as + NTA * ASZ;
        float* bl = bs + BSZ;
#pragma unroll
        for (int i = 0; i < AIT; i++) {
            int e = i * 256 + tid;
            int r = e / AQ, c = (e % AQ) << 2;
            cp16(&as[r * ALD + c], &A[(size_t)(m0 + r) * lda + koff + k0 + c]);
            if (THREE) cp16(&al[r * ALD + c], &Alo[(size_t)(m0 + r) * lda + koff + k0 + c]);
        }
#pragma unroll
        for (int i = 0; i < BIT; i++) {
            int e = i * 256 + tid;
            int r = e / AQ, c = (e % AQ) << 2;
            cp16(&bs[r * ALD + c], &Bm[(size_t)(n0 + r) * ldb + koff + k0 + c]);
            if (THREE) cp16(&bl[r * ALD + c], &Blo[(size_t)(n0 + r) * ldb + koff + k0 + c]);
        }
    };

    load_stage(0, 0);
    cp_commit();

    for (int it = 0; it < iters; it++) {
        if (it + 1 < iters) load_stage((it + 1) & 1, (it + 1) * BKT);
        cp_commit();
        cp_wait<1>();
        __syncthreads();

        const float* as = smem + (it & 1) * STAGE;
        const float* al = as + ASZ;
        const float* bs = as + NTA * ASZ;
        const float* bl = bs + BSZ;

#pragma unroll
        for (int kk = 0; kk < BKT / 8; kk++) {
            wmma::fragment<wmma::matrix_a, 16, 16, 8, wmma::precision::tf32, wmma::row_major> af[2], afl[THREE ? 2 : 1];
            wmma::fragment<wmma::matrix_b, 16, 16, 8, wmma::precision::tf32, wmma::col_major> bf[2], bfl[THREE ? 2 : 1];
#pragma unroll
            for (int i = 0; i < 2; i++) {
                wmma::load_matrix_sync(af[i], &as[(wm * 32 + i * 16) * ALD + kk * 8], ALD);
                if (THREE)
                    wmma::load_matrix_sync(afl[i], &al[(wm * 32 + i * 16) * ALD + kk * 8], ALD);
            }
#pragma unroll
            for (int j = 0; j < 2; j++) {
                wmma::load_matrix_sync(bf[j], &bs[(wn * 32 + j * 16) * ALD + kk * 8], ALD);
                if (THREE)
                    wmma::load_matrix_sync(bfl[j], &bl[(wn * 32 + j * 16) * ALD + kk * 8], ALD);
            }
#pragma unroll
            for (int i = 0; i < 2; i++)
#pragma unroll
                for (int j = 0; j < 2; j++) {
                    if (THREE) {
                        wmma::mma_sync(acc[i][j], af[i], bfl[j], acc[i][j]);
                        wmma::mma_sync(acc[i][j], afl[i], bf[j], acc[i][j]);
                    }
                    wmma::mma_sync(acc[i][j], af[i], bf[j], acc[i][j]);
                }
        }
        __syncthreads();
    }

    constexpr int SLD = BN + 4;
    float* St = smem;
#pragma unroll
    for (int i = 0; i < 2; i++)
#pragma unroll
        for (int j = 0; j < 2; j++)
            wmma::store_matrix_sync(&St[(wm * 32 + i * 16) * SLD + wn * 32 + j * 16],
                                    acc[i][j], SLD, wmma::mem_row_major);
    __syncthreads();
#pragma unroll
    for (int it = 0; it < 8; it++) {
        int e = it * 256 + tid;
        int r = e >> 4, c = (e & 15) << 2;
        float4 v = *(const float4*)&St[r * SLD + c];
        size_t ix = (size_t)blockIdx.z * zstride + (size_t)(m0 + r) * ldc + n0 + c;
        *(float4*)&C[ix] = v;
    }
}

// ---------------- G = W1 @ W1^T in exact fp32 (SIMT, smem-tiled) ----------------
__global__ void __launch_bounds__(256) gram_kernel(const float* __restrict__ W1)
{
    __shared__ float As[32][33], Bs[32][33];
    const int tid = threadIdx.x;
    const int r0 = blockIdx.y * 32, c0 = blockIdx.x * 32;
    const int ty = tid >> 4, tx = tid & 15;
    float a00 = 0.f, a01 = 0.f, a10 = 0.f, a11 = 0.f;

    for (int k0 = 0; k0 < FDIM; k0 += 32) {
#pragma unroll
        for (int i = 0; i < 4; i++) {
            int e = i * 256 + tid;
            int r = e >> 5, c = e & 31;
            As[r][c] = W1[(size_t)(r0 + r) * FDIM + k0 + c];
            Bs[r][c] = W1[(size_t)(c0 + r) * FDIM + k0 + c];
        }
        __syncthreads();
#pragma unroll 8
        for (int k = 0; k < 32; k++) {
            float x0 = As[ty * 2][k],     x1 = As[ty * 2 + 1][k];
            float y0 = Bs[tx * 2][k],     y1 = Bs[tx * 2 + 1][k];
            a00 = fmaf(x0, y0, a00); a01 = fmaf(x0, y1, a01);
            a10 = fmaf(x1, y0, a10); a11 = fmaf(x1, y1, a11);
        }
        __syncthreads();
    }
    int gr = r0 + ty * 2, gc = c0 + tx * 2;
    g_G[gr * HDIM + gc] = a00;       g_G[gr * HDIM + gc + 1] = a01;
    g_G[(gr + 1) * HDIM + gc] = a10; g_G[(gr + 1) * HDIM + gc + 1] = a11;
}

// ---------------- h reduce ----------------
__global__ void __launch_bounds__(256) hreduce_kernel(const float* __restrict__ b1)
{
    int e = blockIdx.x * 256 + threadIdx.x;
    size_t ix = (size_t)e * 4;
    int col = (int)(ix & (HDIM - 1));
    float4 p0 = *(const float4*)&g_hpart[ix];
    float4 p1 = *(const float4*)&g_hpart[(size_t)BATCH * HDIM + ix];
    float4 v;
    v.x = p0.x + p1.x + b1[col];
    v.y = p0.y + p1.y + b1[col + 1];
    v.z = p0.z + p1.z + b1[col + 2];
    v.w = p0.w + p1.w + b1[col + 3];
    *(float4*)&g_h[ix] = v;
}

// ---------------- prep ----------------
__global__ void __launch_bounds__(256) prep_kernel(
    const float* __restrict__ F, const float* __restrict__ T,
    const float* __restrict__ W1, const float* __restrict__ P)
{
    int b = blockIdx.x, tid = threadIdx.x;
    if (b < 8192) {
        __shared__ float s[32][33];
        int j = b >> 10, t = b & 1023;
        int tr = t >> 5, tc = t & 31;
        int x = tid & 31, y = tid >> 5;
        const float* src = T + (size_t)j * FDIM * FDIM;
#pragma unroll
        for (int i = 0; i < 4; i++)
            s[y + i * 8][x] = src[(size_t)(tr * 32 + y + i * 8) * FDIM + tc * 32 + x];
        __syncthreads();
        float* dh = g_Thi + (size_t)j * FDIM * FDIM;
#pragma unroll
        for (int i = 0; i < 4; i++) {
            int n = tc * 32 + y + i * 8, k = tr * 32 + x;
            dh[(size_t)n * FDIM + k] = wmma::__float_to_tf32(s[x][y + i * 8]);
        }
    } else if (b < 10240) {
        size_t base = (size_t)(b - 8192) * 4096 + tid * 16;
#pragma unroll
        for (int q = 0; q < 4; q++) {
            float4 v = *(const float4*)&F[base + q * 4];
            *(float4*)&g_xa[base + q * 4] = v;
            float vv[4] = {v.x, v.y, v.z, v.w};
#pragma unroll
            for (int e = 0; e < 4; e++) {
                size_t ix = base + q * 4 + e;
                float hi = wmma::__float_to_tf32(vv[e]);
                g_fhi[ix] = hi;
                g_flo[ix] = wmma::__float_to_tf32(vv[e] - hi);
            }
        }
    } else if (b < 10304) {
        size_t base = (size_t)(b - 10240) * 4096 + tid * 16;
#pragma unroll
        for (int q = 0; q < 4; q++) {
            float4 v = *(const float4*)&W1[base + q * 4];
            float vv[4] = {v.x, v.y, v.z, v.w};
#pragma unroll
            for (int e = 0; e < 4; e++) {
                size_t ix = base + q * 4 + e;
                float hi = wmma::__float_to_tf32(vv[e]);
                g_W1hi[ix] = hi;
                g_W1lo[ix] = wmma::__float_to_tf32(vv[e] - hi);
            }
        }
    } else {
        size_t base = (size_t)(b - 10304) * 4096 + tid * 16;
#pragma unroll
        for (int q = 0; q < 4; q++) {
            float4 v = *(const float4*)&P[base + q * 4];
            float vv[4] = {v.x, v.y, v.z, v.w};
#pragma unroll
            for (int e = 0; e < 4; e++) {
                size_t ix = base + q * 4 + e;
                float hi = wmma::__float_to_tf32(vv[e]);
                g_Phi[ix] = hi;
                g_Plo[ix] = wmma::__float_to_tf32(vv[e] - hi);
            }
        }
    }
}

// ---------------- proj identity check ----------------
__global__ void projchk_kernel(const float* __restrict__ P)
{
    int e = blockIdx.x * 256 + threadIdx.x;
    int idx4 = e * 4;
    int row = idx4 >> 10;
    float4 v = *(const float4*)&P[idx4];
    float vv[4] = {v.x, v.y, v.z, v.w};
    bool bad = false;
#pragma unroll
    for (int q = 0; q < 4; q++) {
        int col = (idx4 + q) & 1023;
        float exp = (col == row) ? 1.0f : 0.0f;
        if (vv[q] != exp) bad = true;
    }
    if (__syncthreads_or(bad) && threadIdx.x == 0) atomicOr(&g_notident, 1u);
}

// ---------------- split final x (only if proj != I) ----------------
__global__ void __launch_bounds__(256) splitx_kernel(const float* __restrict__ X)
{
    if (g_notident == 0u) return;
    size_t base = (size_t)blockIdx.x * 4096 + threadIdx.x * 16;
#pragma unroll
    for (int q = 0; q < 4; q++) {
        float4 v = *(const float4*)&X[base + q * 4];
        float vv[4] = {v.x, v.y, v.z, v.w};
#pragma unroll
        for (int e = 0; e < 4; e++) {
            size_t ix = base + q * 4 + e;
            float hi = wmma::__float_to_tf32(vv[e]);
            g_fhi[ix] = hi;
            g_flo[ix] = wmma::__float_to_tf32(vv[e] - hi);
        }
    }
}

// ---------------- coeffs ----------------
__global__ void coeffs_kernel(const float* __restrict__ W2, const float* __restrict__ b2)
{
    int tid = threadIdx.x;
    int row = blockIdx.x * 32 + (tid >> 3);
    int k = tid & 7;
    const float* hr = g_h + (size_t)row * HDIM;
    const float* w = W2 + k * HDIM;
    float s = b2[k];
#pragma unroll 8
    for (int h = 0; h < HDIM; h++) s += fmaxf(hr[h], 0.0f) * w[h];
    g_coeffs[row * NTASK + k] = s;
}

// ---------------- unc ----------------
__global__ void __launch_bounds__(256) unc_kernel(const float* __restrict__ W2)
{
    __shared__ float W2s[NTASK * HDIM];
    __shared__ float Gs[HDIM * 32];
    int tid = threadIdx.x, lane = tid & 31, warp = tid >> 5;
    for (int i = tid; i < NTASK * HDIM; i += 256) W2s[i] = W2[i];

    int row = blockIdx.x * 8 + warp;
    const float* hr = g_h + (size_t)row * HDIM;
    unsigned mb[8];
#pragma unroll
    for (int j = 0; j < 8; j++)
        mb[j] = __ballot_sync(0xffffffffu, hr[j * 32 + lane] > 0.0f);

    float u2[8];
#pragma unroll
    for (int k = 0; k < 8; k++) u2[k] = 0.0f;

    for (int c = 0; c < 8; c++) {
        __syncthreads();
        for (int i = tid; i < HDIM * 32; i += 256) {
            int h = i >> 5, l = i & 31;
            Gs[i] = g_G[h * HDIM + c * 32 + l];
        }
        __syncthreads();
        float t[8];
#pragma unroll
        for (int k = 0; k < 8; k++) t[k] = 0.0f;
        for (int h = 0; h < HDIM; h++) {
            if ((mb[h >> 5] >> (h & 31)) & 1u) {
                float gv = Gs[h * 32 + lane];
#pragma unroll
                for (int k = 0; k < 8; k++) t[k] += W2s[k * HDIM + h] * gv;
            }
        }
        int hp = c * 32 + lane;
        if ((mb[hp >> 5] >> (hp & 31)) & 1u) {
#pragma unroll
            for (int k = 0; k < 8; k++) u2[k] += W2s[k * HDIM + hp] * t[k];
        }
    }
#pragma unroll
    for (int k = 0; k < 8; k++) {
        float v = u2[k];
        for (int off = 16; off; off >>= 1) v += __shfl_down_sync(0xffffffffu, v, off);
        if (lane == 0) {
            v = fmaxf(v, 0.0f);
            g_unc2[row * NTASK + k] = v;
            atomicMax(&g_max2bits, __float_as_uint(v));
        }
    }
}

// ---------------- gating + compaction ----------------
__global__ void gate_kernel(const float* __restrict__ bthr, const float* __restrict__ beta)
{
    int i = blockIdx.x * blockDim.x + threadIdx.x;
    if (i >= BATCH * NTASK) return;
    int row = i >> 3, k = i & 7;
    float max2 = __uint_as_float(g_max2bits);
    float u = (max2 > 0.0f) ? sqrtf(g_unc2[i] / max2) : sqrtf(g_unc2[i]);
    float base = log1pf(expf(bthr[0]));
    float thr = base * (1.0f + fmaxf(beta[0], 0.0f) * u);
    float cf = g_coeffs[i];
    float gf = (fabsf(cf) < thr) ? 0.0f : cf;
    g_gated[i] = gf;
    if (gf != 0.0f) {
        int p = atomicAdd(&g_cnt[k], 1);
        g_idx[k * BATCH + p] = row;
    }
}

// ---------------- copy rounded buffer for zero-gate rows ----------------
__global__ void __launch_bounds__(256) copy_round_inactive(
    const float* __restrict__ rin, float* __restrict__ rout, int j)
{
    int row = blockIdx.x;
    if (g_gated[row * NTASK + j] != 0.0f) return;
    size_t b4 = (size_t)row * (FDIM / 4) + threadIdx.x;
    ((float4*)rout)[b4] = ((const float4*)rin)[b4];
}

// ---------------- launch ----------------
extern "C" void kernel_launch(void* const* d_in, const int* in_sizes, int n_in,
                              void* d_out, int out_size)
{
    const float* features = (const float*)d_in[0];
    const float* W1   = (const float*)d_in[1];
    const float* b1   = (const float*)d_in[2];
    const float* W2   = (const float*)d_in[3];
    const float* b2   = (const float*)d_in[4];
    const float* task = (const float*)d_in[5];
    const float* projW = (const float*)d_in[6];
    const float* bthr = (const float*)d_in[7];
    const float* beta = (const float*)d_in[8];
    float* out = (float*)d_out;

    float *fhi, *flo, *w1hi, *w1lo, *thi, *phi, *plo;
    float *xa, *xar, *xbr, *hpart, *gated;
    int *idxp, *cntp;
    void *maxp, *nip;
    cudaGetSymbolAddress((void**)&fhi, g_fhi);   cudaGetSymbolAddress((void**)&flo, g_flo);
    cudaGetSymbolAddress((void**)&w1hi, g_W1hi); cudaGetSymbolAddress((void**)&w1lo, g_W1lo);
    cudaGetSymbolAddress((void**)&thi, g_Thi);
    cudaGetSymbolAddress((void**)&phi, g_Phi);   cudaGetSymbolAddress((void**)&plo, g_Plo);
    cudaGetSymbolAddress((void**)&xa, g_xa);
    cudaGetSymbolAddress((void**)&xar, g_xar);   cudaGetSymbolAddress((void**)&xbr, g_xbr);
    cudaGetSymbolAddress((void**)&hpart, g_hpart);
    cudaGetSymbolAddress((void**)&gated, g_gated);
    cudaGetSymbolAddress((void**)&idxp, g_idx);  cudaGetSymbolAddress((void**)&cntp, g_cnt);
    cudaGetSymbolAddress(&maxp, g_max2bits);     cudaGetSymbolAddress(&nip, g_notident);

    const int smem_h  = 3 * HSTAGE * 4;                       // 92160
    const int smem_p  = 2 * 2 * (BM * 36 + BN * 36) * 4;      // 110592
    const int smem_c  = 3 * CSTAGE * 4;                       // 82944
    cudaFuncSetAttribute(gemm_h, cudaFuncAttributeMaxDynamicSharedMemorySize, smem_h);
    cudaFuncSetAttribute(gemm_tf32<32, true, 5>, cudaFuncAttributeMaxDynamicSharedMemorySize, smem_p);
    cudaFuncSetAttribute(gemm_chain, cudaFuncAttributeMaxDynamicSharedMemorySize, smem_c);

    cudaMemsetAsync(maxp, 0, 4);
    cudaMemsetAsync(cntp, 0, NTASK * sizeof(int));
    cudaMemsetAsync(nip, 0, 4);

    // (1) prep (+x init) and proj identity check
    prep_kernel<<<10560, 256>>>(features, task, W1, projW);
    projchk_kernel<<<1024, 256>>>(projW);

    // (2) G exact fp32
    gram_kernel<<<dim3(8, 8), 256>>>(W1);

    // (3) h: split-K=2, 3-term tf32 manual mma (3-stage), then fixed-order reduce
    gemm_h<<<dim3(HDIM / 64, BATCH / 128, 2), 256, smem_h>>>(
        fhi, flo, w1hi, w1lo, hpart);
    hreduce_kernel<<<BATCH * HDIM / 1024, 256>>>(b1);

    // (4-6) coeffs, unc, gate+compact
    coeffs_kernel<<<BATCH / 32, 256>>>(W2, b2);
    unc_kernel<<<BATCH / 8, 256>>>(W2);
    gate_kernel<<<(BATCH * NTASK + 255) / 256, 256>>>(bthr, beta);

    // (7..) chain: manual-mma gathered GEMM (3-stage), in-place fp32 x, rounded ping-pong
    dim3 gC(FDIM / 64, BATCH / 128);     // 16 x 64
    const float* around = fhi;
    float* nextr = xar;
    for (int j = 0; j < NTASK; j++) {
        copy_round_inactive<<<BATCH, 256>>>(around, nextr, j);
        gemm_chain<<<gC, 256, smem_c>>>(
            around, thi + (size_t)j * FDIM * FDIM, xa, gated, j, nextr,
            idxp + j * BATCH, cntp + j);
        around = nextr;
        nextr = (around == xar) ? xbr : xar;
    }

    // final split (no-op when proj == I)
    splitx_kernel<<<BATCH * FDIM / 4096, 256>>>(xa);

    // proj: identity -> copy, else 3-term GEMM
    gemm_tf32<32, true, 5><<<dim3(FDIM / BN, BATCH / BM), 256, smem_p>>>(
        fhi, flo, FDIM, phi, plo, FDIM, out, FDIM, FDIM, 0, xa);
}